// round 3
// baseline (speedup 1.0000x reference)
#include <cuda_runtime.h>
#include <cuda_bf16.h>
#include <math.h>
#include <stdint.h>

// ---------------- problem constants ----------------
#define B_  2
#define S_  2048
#define E_  1024
#define H_  16
#define HD_ 64
#define FF_ 4096
#define M_  (B_ * S_)          // 4096 rows

// ---------------- fp32 scratch ----------------
__device__ __align__(128) float g_qkv[(size_t)M_ * 3 * E_];
__device__ __align__(128) float g_ctx[(size_t)M_ * E_];
__device__ __align__(128) float g_tmp[(size_t)M_ * E_];
__device__ __align__(128) float g_x1 [(size_t)M_ * E_];
__device__ __align__(128) float g_h  [(size_t)M_ * FF_];

// ---------------- bf16 hi/lo split scratch ----------------
__device__ __align__(128) __nv_bfloat16 g_xh  [(size_t)M_ * E_],  g_xl  [(size_t)M_ * E_];
__device__ __align__(128) __nv_bfloat16 g_ctxh[(size_t)M_ * E_],  g_ctxl[(size_t)M_ * E_];
__device__ __align__(128) __nv_bfloat16 g_x1h [(size_t)M_ * E_],  g_x1l [(size_t)M_ * E_];
__device__ __align__(128) __nv_bfloat16 g_hh  [(size_t)M_ * FF_], g_hl  [(size_t)M_ * FF_];
__device__ __align__(128) __nv_bfloat16 g_wqkvh[(size_t)3 * E_ * E_], g_wqkvl[(size_t)3 * E_ * E_];
__device__ __align__(128) __nv_bfloat16 g_wouth[(size_t)E_ * E_],     g_woutl[(size_t)E_ * E_];
__device__ __align__(128) __nv_bfloat16 g_w1h  [(size_t)FF_ * E_],    g_w1l  [(size_t)FF_ * E_];
__device__ __align__(128) __nv_bfloat16 g_w2h  [(size_t)E_ * FF_],    g_w2l  [(size_t)E_ * FF_];

// ============================================================================
// helpers
// ============================================================================
__device__ __forceinline__ uint32_t smem_u32(const void* p) {
    uint32_t a;
    asm("{ .reg .u64 t; cvta.to.shared.u64 t, %1; cvt.u32.u64 %0, t; }"
        : "=r"(a) : "l"(p));
    return a;
}

__device__ __forceinline__ void cp16(uint32_t dst, const void* src) {
    asm volatile("cp.async.cg.shared.global [%0], [%1], 16;"
                 :: "r"(dst), "l"(src) : "memory");
}
#define CP_COMMIT()  asm volatile("cp.async.commit_group;" ::: "memory")
#define CP_WAIT(N)   asm volatile("cp.async.wait_group %0;" :: "n"(N) : "memory")

__device__ __forceinline__ void ldsm4(uint32_t* r, uint32_t addr) {
    asm volatile("ldmatrix.sync.aligned.m8n8.x4.shared.b16 {%0,%1,%2,%3}, [%4];"
                 : "=r"(r[0]), "=r"(r[1]), "=r"(r[2]), "=r"(r[3]) : "r"(addr));
}

__device__ __forceinline__ void mma16816(float* d, const uint32_t* a, const uint32_t* b) {
    asm volatile(
        "mma.sync.aligned.m16n8k16.row.col.f32.bf16.bf16.f32 "
        "{%0,%1,%2,%3}, {%4,%5,%6,%7}, {%8,%9}, {%0,%1,%2,%3};"
        : "+f"(d[0]), "+f"(d[1]), "+f"(d[2]), "+f"(d[3])
        : "r"(a[0]), "r"(a[1]), "r"(a[2]), "r"(a[3]), "r"(b[0]), "r"(b[1]));
}

// ============================================================================
// Split fp32 -> (bf16 hi, bf16 lo)
// ============================================================================
__global__ __launch_bounds__(256)
void split_kernel(const float* __restrict__ src, __nv_bfloat16* __restrict__ hi,
                  __nv_bfloat16* __restrict__ lo, int n4) {
    int i = blockIdx.x * 256 + threadIdx.x;
    if (i >= n4) return;
    float4 v = ((const float4*)src)[i];
    __nv_bfloat16 h0 = __float2bfloat16(v.x);
    __nv_bfloat16 h1 = __float2bfloat16(v.y);
    __nv_bfloat16 h2 = __float2bfloat16(v.z);
    __nv_bfloat16 h3 = __float2bfloat16(v.w);
    __nv_bfloat16 l0 = __float2bfloat16(v.x - __bfloat162float(h0));
    __nv_bfloat16 l1 = __float2bfloat16(v.y - __bfloat162float(h1));
    __nv_bfloat16 l2 = __float2bfloat16(v.z - __bfloat162float(h2));
    __nv_bfloat16 l3 = __float2bfloat16(v.w - __bfloat162float(h3));
    __nv_bfloat162 a, b;
    a.x = h0; a.y = h1; b.x = h2; b.y = h3;
    ((__nv_bfloat162*)hi)[2 * i]     = a;
    ((__nv_bfloat162*)hi)[2 * i + 1] = b;
    a.x = l0; a.y = l1; b.x = l2; b.y = l3;
    ((__nv_bfloat162*)lo)[2 * i]     = a;
    ((__nv_bfloat162*)lo)[2 * i + 1] = b;
}

// ============================================================================
// mma.sync GEMM: C[M,N] = (Ah+Al)[M,K] @ (Bh+Bl)[N,K]^T + bias, optional GELU
// CTA 128x128, K-tile 32, 8 warps (2 M x 4 N), warp tile 64x32.
// 2-stage cp.async double buffering. 3-term bf16 split.
// ============================================================================
#define PAD   40                          // bf16 per smem row (32 data + 8 pad)
#define TILE_BYTES (128 * PAD * 2)        // 10240
#define STAGE_BYTES (4 * TILE_BYTES)      // Ah, Al, Bh, Bl
#define GSMEM_TOTAL (2 * STAGE_BYTES)     // 81920

template<int ACT>
__global__ __launch_bounds__(256)
void mma_gemm(const __nv_bfloat16* __restrict__ Ah, const __nv_bfloat16* __restrict__ Al,
              const __nv_bfloat16* __restrict__ Bh, const __nv_bfloat16* __restrict__ Bl,
              const float* __restrict__ bias, float* __restrict__ C,
              int M, int N, int K) {
    extern __shared__ char smem[];
    const uint32_t sbase = smem_u32(smem);
    const int tid  = threadIdx.x;
    const int bm   = blockIdx.y * 128;
    const int bn   = blockIdx.x * 128;

    const int wid  = tid >> 5;
    const int lane = tid & 31;
    const int wm   = (wid & 1) * 64;     // warp m offset
    const int wn   = (wid >> 1) * 32;    // warp n offset
    const int g    = lane >> 3;          // ldmatrix group
    const int rig  = lane & 7;           // row in group

    const __nv_bfloat16* srcs[4] = {
        Ah + (size_t)bm * K, Al + (size_t)bm * K,
        Bh + (size_t)bn * K, Bl + (size_t)bn * K };

    float acc[4][4][4];
#pragma unroll
    for (int i = 0; i < 4; i++)
#pragma unroll
        for (int j = 0; j < 4; j++)
#pragma unroll
            for (int r = 0; r < 4; r++) acc[i][j][r] = 0.f;

    const int nt = K >> 5;   // k-tiles of 32

    auto load_stage = [&](int kt, int st) {
        const uint32_t sdst = sbase + st * STAGE_BYTES;
        const int koff = kt * 32;
#pragma unroll
        for (int t = 0; t < 8; t++) {
            const int tile = t >> 1;
            const int idx  = ((t & 1) << 8) + tid;     // 0..511
            const int row  = idx >> 2;
            const int c4   = idx & 3;
            cp16(sdst + tile * TILE_BYTES + (row * PAD + c4 * 8) * 2,
                 srcs[tile] + (size_t)row * K + koff + c4 * 8);
        }
    };

    load_stage(0, 0);
    CP_COMMIT();

    for (int kt = 0; kt < nt; kt++) {
        if (kt + 1 < nt) {
            load_stage(kt + 1, (kt + 1) & 1);
            CP_COMMIT();
            CP_WAIT(1);
        } else {
            CP_WAIT(0);
        }
        __syncthreads();

        const uint32_t st = sbase + (kt & 1) * STAGE_BYTES;
        const uint32_t sAh = st;
        const uint32_t sAl = st + TILE_BYTES;
        const uint32_t sBh = st + 2 * TILE_BYTES;
        const uint32_t sBl = st + 3 * TILE_BYTES;

#pragma unroll
        for (int ks = 0; ks < 2; ks++) {
            const int k0 = ks * 16;
            uint32_t ah[4][4], al[4][4], bh[2][4], bl[2][4];
            // A: row = wm + i*16 + (g&1)*8 + rig, col = k0 + (g>>1)*8
            const uint32_t aoff = ((wm + (g & 1) * 8 + rig) * PAD + k0 + (g >> 1) * 8) * 2;
#pragma unroll
            for (int i = 0; i < 4; i++) {
                ldsm4(ah[i], sAh + aoff + i * 16 * PAD * 2);
                ldsm4(al[i], sAl + aoff + i * 16 * PAD * 2);
            }
            // B: row = wn + j2*16 + (g>>1)*8 + rig, col = k0 + (g&1)*8
            const uint32_t boff = ((wn + (g >> 1) * 8 + rig) * PAD + k0 + (g & 1) * 8) * 2;
#pragma unroll
            for (int j2 = 0; j2 < 2; j2++) {
                ldsm4(bh[j2], sBh + boff + j2 * 16 * PAD * 2);
                ldsm4(bl[j2], sBl + boff + j2 * 16 * PAD * 2);
            }
#pragma unroll
            for (int i = 0; i < 4; i++)
#pragma unroll
                for (int j = 0; j < 4; j++) {
                    const uint32_t* ph = &bh[j >> 1][(j & 1) * 2];
                    const uint32_t* pl = &bl[j >> 1][(j & 1) * 2];
                    mma16816(acc[i][j], ah[i], ph);
                    mma16816(acc[i][j], ah[i], pl);
                    mma16816(acc[i][j], al[i], ph);
                }
        }
        __syncthreads();
    }

    // epilogue: bias (+GELU), direct stores from fragments
    const int m_l = lane >> 2;
    const int n_l = (lane & 3) * 2;
#pragma unroll
    for (int j = 0; j < 4; j++) {
        const int n = bn + wn + j * 8 + n_l;
        const float2 b2 = *(const float2*)(bias + n);
#pragma unroll
        for (int i = 0; i < 4; i++) {
            const int m = bm + wm + i * 16 + m_l;
            float v0 = acc[i][j][0] + b2.x;
            float v1 = acc[i][j][1] + b2.y;
            float v2 = acc[i][j][2] + b2.x;
            float v3 = acc[i][j][3] + b2.y;
            if (ACT == 1) {
                v0 = 0.5f * v0 * (1.0f + erff(v0 * 0.70710678118654752f));
                v1 = 0.5f * v1 * (1.0f + erff(v1 * 0.70710678118654752f));
                v2 = 0.5f * v2 * (1.0f + erff(v2 * 0.70710678118654752f));
                v3 = 0.5f * v3 * (1.0f + erff(v3 * 0.70710678118654752f));
            }
            float2 o0; o0.x = v0; o0.y = v1;
            float2 o1; o1.x = v2; o1.y = v3;
            *(float2*)(C + (size_t)m * N + n)       = o0;
            *(float2*)(C + (size_t)(m + 8) * N + n) = o1;
        }
    }
}

// ============================================================================
// Flash attention (fp32 CUDA-core)
// ============================================================================
#define APAD 68

__global__ __launch_bounds__(256)
void attn_kernel(const float* __restrict__ qkv, float* __restrict__ ctx) {
    extern __shared__ float sm[];
    float* Qs  = sm;
    float* Ks  = Qs  + 64 * APAD;
    float* Vs  = Ks  + 64 * APAD;
    float* red = Vs  + 64 * APAD;
    float* mrow = red + 64 * 16;
    float* lrow = mrow + 64;
    float* arow = lrow + 64;

    const int q0 = blockIdx.x * 64;
    const int h  = blockIdx.y;
    const int b  = blockIdx.z;
    const int tid = threadIdx.x;
    const int tx = tid & 15;
    const int ty = tid >> 4;

    const int LD = 3 * E_;
    const float* base = qkv + (size_t)b * S_ * LD + h * (3 * HD_);

    {
        const int r  = tid >> 2;
        const int c0 = (tid & 3) * 16;
        const float* src = base + (size_t)(q0 + r) * LD + c0;
        float* dst = Qs + r * APAD + c0;
#pragma unroll
        for (int j = 0; j < 16; j += 4)
            *(float4*)(dst + j) = *(const float4*)(src + j);
    }
    if (tid < 64) { mrow[tid] = -1e30f; lrow[tid] = 0.f; }

    float acc[4][4];
#pragma unroll
    for (int i = 0; i < 4; i++)
#pragma unroll
        for (int j = 0; j < 4; j++) acc[i][j] = 0.f;

    for (int kt = 0; kt < S_ / 64; kt++) {
        const int k0 = kt * 64;
        __syncthreads();
        {
            const int r  = tid >> 2;
            const int c0 = (tid & 3) * 16;
            const float* srck = base + (size_t)(k0 + r) * LD + HD_ + c0;
            const float* srcv = base + (size_t)(k0 + r) * LD + 2 * HD_ + c0;
            float* dk = Ks + r * APAD + c0;
            float* dv = Vs + r * APAD + c0;
#pragma unroll
            for (int j = 0; j < 16; j += 4) {
                *(float4*)(dk + j) = *(const float4*)(srck + j);
                *(float4*)(dv + j) = *(const float4*)(srcv + j);
            }
        }
        __syncthreads();

        float s[4][4];
#pragma unroll
        for (int i = 0; i < 4; i++)
#pragma unroll
            for (int j = 0; j < 4; j++) s[i][j] = 0.f;

        for (int d = 0; d < 64; d++) {
            float qv[4], kv[4];
#pragma unroll
            for (int i = 0; i < 4; i++) qv[i] = Qs[(ty * 4 + i) * APAD + d];
#pragma unroll
            for (int j = 0; j < 4; j++) kv[j] = Ks[(tx * 4 + j) * APAD + d];
#pragma unroll
            for (int i = 0; i < 4; i++)
#pragma unroll
                for (int j = 0; j < 4; j++)
                    s[i][j] = fmaf(qv[i], kv[j], s[i][j]);
        }
        const float scale = 0.125f;
#pragma unroll
        for (int i = 0; i < 4; i++)
#pragma unroll
            for (int j = 0; j < 4; j++) s[i][j] *= scale;

#pragma unroll
        for (int i = 0; i < 4; i++) {
            float t = s[i][0];
#pragma unroll
            for (int j = 1; j < 4; j++) t = fmaxf(t, s[i][j]);
            red[(ty * 4 + i) * 16 + tx] = t;
        }
        __syncthreads();
        if (tid < 64) {
            float mx = red[tid * 16];
#pragma unroll
            for (int t = 1; t < 16; t++) mx = fmaxf(mx, red[tid * 16 + t]);
            float mold = mrow[tid];
            float mnew = fmaxf(mold, mx);
            mrow[tid] = mnew;
            arow[tid] = __expf(mold - mnew);
        }
        __syncthreads();

        float a_i[4], m_i[4], psum[4];
#pragma unroll
        for (int i = 0; i < 4; i++) {
            a_i[i] = arow[ty * 4 + i];
            m_i[i] = mrow[ty * 4 + i];
            psum[i] = 0.f;
        }
#pragma unroll
        for (int i = 0; i < 4; i++) {
#pragma unroll
            for (int j = 0; j < 4; j++) {
                float p = __expf(s[i][j] - m_i[i]);
                Ks[(ty * 4 + i) * APAD + tx * 4 + j] = p;
                psum[i] += p;
                acc[i][j] *= a_i[i];
            }
            red[(ty * 4 + i) * 16 + tx] = psum[i];
        }
        __syncthreads();
        if (tid < 64) {
            float ssum = 0.f;
#pragma unroll
            for (int t = 0; t < 16; t++) ssum += red[tid * 16 + t];
            lrow[tid] = lrow[tid] * arow[tid] + ssum;
        }

        for (int kk = 0; kk < 64; kk++) {
            float pv[4], vv[4];
#pragma unroll
            for (int i = 0; i < 4; i++) pv[i] = Ks[(ty * 4 + i) * APAD + kk];
#pragma unroll
            for (int j = 0; j < 4; j++) vv[j] = Vs[kk * APAD + tx * 4 + j];
#pragma unroll
            for (int i = 0; i < 4; i++)
#pragma unroll
                for (int j = 0; j < 4; j++)
                    acc[i][j] = fmaf(pv[i], vv[j], acc[i][j]);
        }
    }
    __syncthreads();

#pragma unroll
    for (int i = 0; i < 4; i++) {
        const int r = ty * 4 + i;
        const float linv = 1.0f / lrow[r];
        float* dst = ctx + ((size_t)b * S_ + q0 + r) * E_ + h * HD_ + tx * 4;
        float4 o;
        o.x = acc[i][0] * linv; o.y = acc[i][1] * linv;
        o.z = acc[i][2] * linv; o.w = acc[i][3] * linv;
        *(float4*)dst = o;
    }
}

// ============================================================================
// Fused residual-add + LayerNorm over E=1024
// ============================================================================
__global__ __launch_bounds__(256)
void add_ln_kernel(const float* __restrict__ x, const float* __restrict__ y,
                   const float* __restrict__ g, const float* __restrict__ beta,
                   float* __restrict__ out) {
    __shared__ float red1[8], red2[8];
    __shared__ float s_mean, s_rstd;
    const int row = blockIdx.x;
    const int tid = threadIdx.x;

    const float4 xv = ((const float4*)(x + (size_t)row * E_))[tid];
    const float4 yv = ((const float4*)(y + (size_t)row * E_))[tid];
    float v0 = xv.x + yv.x, v1 = xv.y + yv.y, v2 = xv.z + yv.z, v3 = xv.w + yv.w;

    float s  = v0 + v1 + v2 + v3;
    float ss = v0 * v0 + v1 * v1 + v2 * v2 + v3 * v3;
#pragma unroll
    for (int o = 16; o > 0; o >>= 1) {
        s  += __shfl_down_sync(0xffffffffu, s, o);
        ss += __shfl_down_sync(0xffffffffu, ss, o);
    }
    const int warp = tid >> 5, lane = tid & 31;
    if (lane == 0) { red1[warp] = s; red2[warp] = ss; }
    __syncthreads();
    if (tid == 0) {
        float ts = 0.f, tss = 0.f;
#pragma unroll
        for (int w = 0; w < 8; w++) { ts += red1[w]; tss += red2[w]; }
        float mean = ts * (1.0f / E_);
        float var  = tss * (1.0f / E_) - mean * mean;
        s_mean = mean;
        s_rstd = rsqrtf(var + 1e-5f);
    }
    __syncthreads();
    const float mean = s_mean, rstd = s_rstd;

    const float4 gv = ((const float4*)g)[tid];
    const float4 bv = ((const float4*)beta)[tid];
    float4 o;
    o.x = (v0 - mean) * rstd * gv.x + bv.x;
    o.y = (v1 - mean) * rstd * gv.y + bv.y;
    o.z = (v2 - mean) * rstd * gv.z + bv.z;
    o.w = (v3 - mean) * rstd * gv.w + bv.w;
    ((float4*)(out + (size_t)row * E_))[tid] = o;
}

// ============================================================================
// Launch
// ============================================================================
extern "C" void kernel_launch(void* const* d_in, const int* in_sizes, int n_in,
                              void* d_out, int out_size) {
    const float* x     = (const float*)d_in[0];
    const float* w_qkv = (const float*)d_in[1];
    const float* b_qkv = (const float*)d_in[2];
    const float* w_out = (const float*)d_in[3];
    const float* b_out = (const float*)d_in[4];
    const float* g1    = (const float*)d_in[5];
    const float* beta1 = (const float*)d_in[6];
    const float* g2    = (const float*)d_in[7];
    const float* beta2 = (const float*)d_in[8];
    const float* w1    = (const float*)d_in[9];
    const float* bf1   = (const float*)d_in[10];
    const float* w2    = (const float*)d_in[11];
    const float* bf2   = (const float*)d_in[12];
    float* out = (float*)d_out;

    float *qkv, *ctx, *tmp, *x1, *hbuf;
    cudaGetSymbolAddress((void**)&qkv,  g_qkv);
    cudaGetSymbolAddress((void**)&ctx,  g_ctx);
    cudaGetSymbolAddress((void**)&tmp,  g_tmp);
    cudaGetSymbolAddress((void**)&x1,   g_x1);
    cudaGetSymbolAddress((void**)&hbuf, g_h);

    __nv_bfloat16 *xh, *xl, *ctxh, *ctxl, *x1h, *x1l, *hh, *hl;
    __nv_bfloat16 *wqkvh, *wqkvl, *wouth, *woutl, *w1h, *w1l, *w2h, *w2l;
    cudaGetSymbolAddress((void**)&xh, g_xh);     cudaGetSymbolAddress((void**)&xl, g_xl);
    cudaGetSymbolAddress((void**)&ctxh, g_ctxh); cudaGetSymbolAddress((void**)&ctxl, g_ctxl);
    cudaGetSymbolAddress((void**)&x1h, g_x1h);   cudaGetSymbolAddress((void**)&x1l, g_x1l);
    cudaGetSymbolAddress((void**)&hh, g_hh);     cudaGetSymbolAddress((void**)&hl, g_hl);
    cudaGetSymbolAddress((void**)&wqkvh, g_wqkvh); cudaGetSymbolAddress((void**)&wqkvl, g_wqkvl);
    cudaGetSymbolAddress((void**)&wouth, g_wouth); cudaGetSymbolAddress((void**)&woutl, g_woutl);
    cudaGetSymbolAddress((void**)&w1h, g_w1h);   cudaGetSymbolAddress((void**)&w1l, g_w1l);
    cudaGetSymbolAddress((void**)&w2h, g_w2h);   cudaGetSymbolAddress((void**)&w2l, g_w2l);

    const int attn_smem = (3 * 64 * APAD + 64 * 16 + 3 * 64) * (int)sizeof(float);
    cudaFuncSetAttribute(attn_kernel, cudaFuncAttributeMaxDynamicSharedMemorySize, attn_smem);
    cudaFuncSetAttribute(mma_gemm<0>, cudaFuncAttributeMaxDynamicSharedMemorySize, GSMEM_TOTAL);
    cudaFuncSetAttribute(mma_gemm<1>, cudaFuncAttributeMaxDynamicSharedMemorySize, GSMEM_TOTAL);

    dim3 thr(256);
    auto split = [&](const float* s, __nv_bfloat16* h, __nv_bfloat16* l, size_t n) {
        int n4 = (int)(n / 4);
        split_kernel<<<(n4 + 255) / 256, 256>>>(s, h, l, n4);
    };

    // weight splits
    split(w_qkv, wqkvh, wqkvl, (size_t)3 * E_ * E_);
    split(w_out, wouth, woutl, (size_t)E_ * E_);
    split(w1,    w1h,   w1l,   (size_t)FF_ * E_);
    split(w2,    w2h,   w2l,   (size_t)E_ * FF_);

    // 1) qkv = x @ w_qkv^T + b_qkv
    split(x, xh, xl, (size_t)M_ * E_);
    mma_gemm<0><<<dim3(3 * E_ / 128, M_ / 128), thr, GSMEM_TOTAL>>>(
        xh, xl, wqkvh, wqkvl, b_qkv, qkv, M_, 3 * E_, E_);

    // 2) flash attention -> ctx
    attn_kernel<<<dim3(S_ / 64, H_, B_), thr, attn_smem>>>(qkv, ctx);

    // 3) out-proj + residual LN -> x1
    split(ctx, ctxh, ctxl, (size_t)M_ * E_);
    mma_gemm<0><<<dim3(E_ / 128, M_ / 128), thr, GSMEM_TOTAL>>>(
        ctxh, ctxl, wouth, woutl, b_out, tmp, M_, E_, E_);
    add_ln_kernel<<<M_, thr>>>(x, tmp, g1, beta1, x1);

    // 4) h = gelu(x1 @ w1^T + bf1)
    split(x1, x1h, x1l, (size_t)M_ * E_);
    mma_gemm<1><<<dim3(FF_ / 128, M_ / 128), thr, GSMEM_TOTAL>>>(
        x1h, x1l, w1h, w1l, bf1, hbuf, M_, FF_, E_);

    // 5) ffn2 + residual LN -> out
    split(hbuf, hh, hl, (size_t)M_ * FF_);
    mma_gemm<0><<<dim3(E_ / 128, M_ / 128), thr, GSMEM_TOTAL>>>(
        hh, hl, w2h, w2l, bf2, tmp, M_, E_, FF_);
    add_ln_kernel<<<M_, thr>>>(x1, tmp, g2, beta2, out);
}

// round 4
// speedup vs baseline: 1.6141x; 1.6141x over previous
#include <cuda_runtime.h>
#include <cuda_bf16.h>
#include <math.h>
#include <stdint.h>

// ---------------- problem constants ----------------
#define B_  2
#define S_  2048
#define E_  1024
#define H_  16
#define HD_ 64
#define FF_ 4096
#define M_  (B_ * S_)          // 4096 rows

// ---------------- fp32 scratch ----------------
__device__ __align__(128) float g_qkv[(size_t)M_ * 3 * E_];
__device__ __align__(128) float g_tmp[(size_t)M_ * E_];
__device__ __align__(128) float g_x1 [(size_t)M_ * E_];

// ---------------- bf16 hi/lo split scratch ----------------
__device__ __align__(128) __nv_bfloat16 g_xh  [(size_t)M_ * E_],  g_xl  [(size_t)M_ * E_];
__device__ __align__(128) __nv_bfloat16 g_ctxh[(size_t)M_ * E_],  g_ctxl[(size_t)M_ * E_];
__device__ __align__(128) __nv_bfloat16 g_x1h [(size_t)M_ * E_],  g_x1l [(size_t)M_ * E_];
__device__ __align__(128) __nv_bfloat16 g_hh  [(size_t)M_ * FF_], g_hl  [(size_t)M_ * FF_];
__device__ __align__(128) __nv_bfloat16 g_wqkvh[(size_t)3 * E_ * E_], g_wqkvl[(size_t)3 * E_ * E_];
__device__ __align__(128) __nv_bfloat16 g_wouth[(size_t)E_ * E_],     g_woutl[(size_t)E_ * E_];
__device__ __align__(128) __nv_bfloat16 g_w1h  [(size_t)FF_ * E_],    g_w1l  [(size_t)FF_ * E_];
__device__ __align__(128) __nv_bfloat16 g_w2h  [(size_t)E_ * FF_],    g_w2l  [(size_t)E_ * FF_];

// ============================================================================
// helpers
// ============================================================================
__device__ __forceinline__ uint32_t smem_u32(const void* p) {
    uint32_t a;
    asm("{ .reg .u64 t; cvta.to.shared.u64 t, %1; cvt.u32.u64 %0, t; }"
        : "=r"(a) : "l"(p));
    return a;
}

__device__ __forceinline__ void cp16(uint32_t dst, const void* src) {
    asm volatile("cp.async.cg.shared.global [%0], [%1], 16;"
                 :: "r"(dst), "l"(src) : "memory");
}
#define CP_COMMIT()  asm volatile("cp.async.commit_group;" ::: "memory")
#define CP_WAIT(N)   asm volatile("cp.async.wait_group %0;" :: "n"(N) : "memory")

__device__ __forceinline__ void ldsm4(uint32_t* r, uint32_t addr) {
    asm volatile("ldmatrix.sync.aligned.m8n8.x4.shared.b16 {%0,%1,%2,%3}, [%4];"
                 : "=r"(r[0]), "=r"(r[1]), "=r"(r[2]), "=r"(r[3]) : "r"(addr));
}

__device__ __forceinline__ void mma16816(float d[4], const uint32_t a[4],
                                         uint32_t b0, uint32_t b1) {
    asm volatile(
        "mma.sync.aligned.m16n8k16.row.col.f32.bf16.bf16.f32 "
        "{%0,%1,%2,%3}, {%4,%5,%6,%7}, {%8,%9}, {%0,%1,%2,%3};"
        : "+f"(d[0]), "+f"(d[1]), "+f"(d[2]), "+f"(d[3])
        : "r"(a[0]), "r"(a[1]), "r"(a[2]), "r"(a[3]), "r"(b0), "r"(b1));
}

__device__ __forceinline__ void split2(float v, __nv_bfloat16& h, __nv_bfloat16& l) {
    h = __float2bfloat16(v);
    l = __float2bfloat16(v - __bfloat162float(h));
}

// ============================================================================
// Split fp32 -> (bf16 hi, bf16 lo)
// ============================================================================
__global__ __launch_bounds__(256)
void split_kernel(const float* __restrict__ src, __nv_bfloat16* __restrict__ hi,
                  __nv_bfloat16* __restrict__ lo, int n4) {
    int i = blockIdx.x * 256 + threadIdx.x;
    if (i >= n4) return;
    float4 v = ((const float4*)src)[i];
    __nv_bfloat16 h0, h1, h2, h3, l0, l1, l2, l3;
    split2(v.x, h0, l0); split2(v.y, h1, l1);
    split2(v.z, h2, l2); split2(v.w, h3, l3);
    __nv_bfloat162 a, b;
    a.x = h0; a.y = h1; b.x = h2; b.y = h3;
    ((__nv_bfloat162*)hi)[2 * i]     = a;
    ((__nv_bfloat162*)hi)[2 * i + 1] = b;
    a.x = l0; a.y = l1; b.x = l2; b.y = l3;
    ((__nv_bfloat162*)lo)[2 * i]     = a;
    ((__nv_bfloat162*)lo)[2 * i + 1] = b;
}

// ============================================================================
// mma.sync GEMM: C = (Ah+Al)[M,K] @ (Bh+Bl)[N,K]^T + bias  (3-term bf16 split)
// CTA 128x128, K-tile 32, 8 warps (2Mx4N), warp tile 64x32, 3-stage cp.async.
// ACT: 0 = none, 1 = exact GELU.  OUT: 0 = fp32 C, 1 = bf16 hi/lo pair.
// ============================================================================
#define PAD   40                          // bf16 per smem row (32 data + 8 pad)
#define TILE_BYTES (128 * PAD * 2)        // 10240
#define STAGE_BYTES (4 * TILE_BYTES)      // Ah, Al, Bh, Bl
#define NSTAGE 3
#define GSMEM_TOTAL (NSTAGE * STAGE_BYTES)  // 122880

template<int ACT, int OUT>
__global__ __launch_bounds__(256, 1)
void mma_gemm(const __nv_bfloat16* __restrict__ Ah, const __nv_bfloat16* __restrict__ Al,
              const __nv_bfloat16* __restrict__ Bh, const __nv_bfloat16* __restrict__ Bl,
              const float* __restrict__ bias,
              float* __restrict__ C,
              __nv_bfloat16* __restrict__ Ch, __nv_bfloat16* __restrict__ Cl,
              int M, int N, int K) {
    extern __shared__ char smem[];
    const uint32_t sbase = smem_u32(smem);
    const int tid  = threadIdx.x;
    const int bm   = blockIdx.y * 128;
    const int bn   = blockIdx.x * 128;

    const int wid  = tid >> 5;
    const int lane = tid & 31;
    const int wm   = (wid & 1) * 64;
    const int wn   = (wid >> 1) * 32;
    const int g    = lane >> 3;
    const int rig  = lane & 7;

    const __nv_bfloat16* srcA_h = Ah + (size_t)bm * K;
    const __nv_bfloat16* srcA_l = Al + (size_t)bm * K;
    const __nv_bfloat16* srcB_h = Bh + (size_t)bn * K;
    const __nv_bfloat16* srcB_l = Bl + (size_t)bn * K;

    float acc[4][4][4];
#pragma unroll
    for (int i = 0; i < 4; i++)
#pragma unroll
        for (int j = 0; j < 4; j++)
#pragma unroll
            for (int r = 0; r < 4; r++) acc[i][j][r] = 0.f;

    const int nt = K >> 5;

    // per-thread load slots (2 rows x 4 chunks across 256 threads per tile)
    const int lrow = tid >> 2;        // 0..63? no: tid>>2 = 0..63 for 256? -> 0..63
    // 256 threads, each does 2 rows per tile: rows tid>>2 and 64+(tid>>2)
    const int lc4  = (tid & 3);

    auto load_stage = [&](int kt, int st) {
        const uint32_t sdst = sbase + st * STAGE_BYTES;
        const size_t koff = (size_t)kt * 32 + lc4 * 8;
        const uint32_t so = lc4 * 16;
#pragma unroll
        for (int half = 0; half < 2; half++) {
            const int row = lrow + half * 64;
            const uint32_t rowo = row * PAD * 2 + so;
            const size_t gof = (size_t)row * K + koff;
            cp16(sdst + 0 * TILE_BYTES + rowo, srcA_h + gof);
            cp16(sdst + 1 * TILE_BYTES + rowo, srcA_l + gof);
            cp16(sdst + 2 * TILE_BYTES + rowo, srcB_h + gof);
            cp16(sdst + 3 * TILE_BYTES + rowo, srcB_l + gof);
        }
    };

    load_stage(0, 0); CP_COMMIT();
    load_stage(1, 1); CP_COMMIT();

    // precomputed ldsm offsets (within a tile)
    const uint32_t aoff = ((wm + (g & 1) * 8 + rig) * PAD + (g >> 1) * 8) * 2;
    const uint32_t boff = ((wn + (g >> 1) * 8 + rig) * PAD + (g & 1) * 8) * 2;

    for (int kt = 0; kt < nt; kt++) {
        if (kt + 2 < nt) load_stage(kt + 2, (kt + 2) % NSTAGE);
        CP_COMMIT();
        CP_WAIT(2);
        __syncthreads();

        const uint32_t st  = sbase + (kt % NSTAGE) * STAGE_BYTES;
        const uint32_t sAh = st;
        const uint32_t sAl = st + TILE_BYTES;
        const uint32_t sBh = st + 2 * TILE_BYTES;
        const uint32_t sBl = st + 3 * TILE_BYTES;

#pragma unroll
        for (int ks = 0; ks < 2; ks++) {
            const uint32_t ko = ks * 32;   // 16 cols * 2B
            uint32_t a0[4][4], b0[2][4];

            // ---- term 1: Ah x Bh ----
#pragma unroll
            for (int i = 0; i < 4; i++) ldsm4(a0[i], sAh + aoff + ko + i * 16 * PAD * 2);
#pragma unroll
            for (int j2 = 0; j2 < 2; j2++) ldsm4(b0[j2], sBh + boff + ko + j2 * 16 * PAD * 2);
#pragma unroll
            for (int i = 0; i < 4; i++)
#pragma unroll
                for (int j = 0; j < 4; j++)
                    mma16816(acc[i][j], a0[i], b0[j >> 1][(j & 1) * 2], b0[j >> 1][(j & 1) * 2 + 1]);

            // ---- term 2: Al x Bh (reuse b0) ----
            uint32_t a1[4][4];
#pragma unroll
            for (int i = 0; i < 4; i++) ldsm4(a1[i], sAl + aoff + ko + i * 16 * PAD * 2);
#pragma unroll
            for (int i = 0; i < 4; i++)
#pragma unroll
                for (int j = 0; j < 4; j++)
                    mma16816(acc[i][j], a1[i], b0[j >> 1][(j & 1) * 2], b0[j >> 1][(j & 1) * 2 + 1]);

            // ---- term 3: Ah x Bl (overwrite b0 with Bl) ----
#pragma unroll
            for (int j2 = 0; j2 < 2; j2++) ldsm4(b0[j2], sBl + boff + ko + j2 * 16 * PAD * 2);
#pragma unroll
            for (int i = 0; i < 4; i++)
#pragma unroll
                for (int j = 0; j < 4; j++)
                    mma16816(acc[i][j], a0[i], b0[j >> 1][(j & 1) * 2], b0[j >> 1][(j & 1) * 2 + 1]);
        }
        __syncthreads();
    }

    // epilogue
    const int m_l = lane >> 2;
    const int n_l = (lane & 3) * 2;
#pragma unroll
    for (int j = 0; j < 4; j++) {
        const int n = bn + wn + j * 8 + n_l;
        const float2 b2 = *(const float2*)(bias + n);
#pragma unroll
        for (int i = 0; i < 4; i++) {
            const int m = bm + wm + i * 16 + m_l;
            float v[4];
            v[0] = acc[i][j][0] + b2.x;
            v[1] = acc[i][j][1] + b2.y;
            v[2] = acc[i][j][2] + b2.x;
            v[3] = acc[i][j][3] + b2.y;
            if (ACT == 1) {
#pragma unroll
                for (int r = 0; r < 4; r++)
                    v[r] = 0.5f * v[r] * (1.0f + erff(v[r] * 0.70710678118654752f));
            }
            if (OUT == 0) {
                float2 o0; o0.x = v[0]; o0.y = v[1];
                float2 o1; o1.x = v[2]; o1.y = v[3];
                *(float2*)(C + (size_t)m * N + n)       = o0;
                *(float2*)(C + (size_t)(m + 8) * N + n) = o1;
            } else {
                __nv_bfloat162 h0, l0, h1, l1;
                split2(v[0], h0.x, l0.x); split2(v[1], h0.y, l0.y);
                split2(v[2], h1.x, l1.x); split2(v[3], h1.y, l1.y);
                *(__nv_bfloat162*)(Ch + (size_t)m * N + n)       = h0;
                *(__nv_bfloat162*)(Cl + (size_t)m * N + n)       = l0;
                *(__nv_bfloat162*)(Ch + (size_t)(m + 8) * N + n) = h1;
                *(__nv_bfloat162*)(Cl + (size_t)(m + 8) * N + n) = l1;
            }
        }
    }
}

// ============================================================================
// Flash attention (fp32 CUDA-core) -> emits ctx as bf16 hi/lo
// ============================================================================
#define APAD 68

__global__ __launch_bounds__(256)
void attn_kernel(const float* __restrict__ qkv,
                 __nv_bfloat16* __restrict__ ctxh, __nv_bfloat16* __restrict__ ctxl) {
    extern __shared__ float sm[];
    float* Qs  = sm;
    float* Ks  = Qs  + 64 * APAD;
    float* Vs  = Ks  + 64 * APAD;
    float* red = Vs  + 64 * APAD;
    float* mrow = red + 64 * 16;
    float* lrow = mrow + 64;
    float* arow = lrow + 64;

    const int q0 = blockIdx.x * 64;
    const int h  = blockIdx.y;
    const int b  = blockIdx.z;
    const int tid = threadIdx.x;
    const int tx = tid & 15;
    const int ty = tid >> 4;

    const int LD = 3 * E_;
    const float* base = qkv + (size_t)b * S_ * LD + h * (3 * HD_);

    {
        const int r  = tid >> 2;
        const int c0 = (tid & 3) * 16;
        const float* src = base + (size_t)(q0 + r) * LD + c0;
        float* dst = Qs + r * APAD + c0;
#pragma unroll
        for (int j = 0; j < 16; j += 4)
            *(float4*)(dst + j) = *(const float4*)(src + j);
    }
    if (tid < 64) { mrow[tid] = -1e30f; lrow[tid] = 0.f; }

    float acc[4][4];
#pragma unroll
    for (int i = 0; i < 4; i++)
#pragma unroll
        for (int j = 0; j < 4; j++) acc[i][j] = 0.f;

    for (int kt = 0; kt < S_ / 64; kt++) {
        const int k0 = kt * 64;
        __syncthreads();
        {
            const int r  = tid >> 2;
            const int c0 = (tid & 3) * 16;
            const float* srck = base + (size_t)(k0 + r) * LD + HD_ + c0;
            const float* srcv = base + (size_t)(k0 + r) * LD + 2 * HD_ + c0;
            float* dk = Ks + r * APAD + c0;
            float* dv = Vs + r * APAD + c0;
#pragma unroll
            for (int j = 0; j < 16; j += 4) {
                *(float4*)(dk + j) = *(const float4*)(srck + j);
                *(float4*)(dv + j) = *(const float4*)(srcv + j);
            }
        }
        __syncthreads();

        float s[4][4];
#pragma unroll
        for (int i = 0; i < 4; i++)
#pragma unroll
            for (int j = 0; j < 4; j++) s[i][j] = 0.f;

        for (int d = 0; d < 64; d++) {
            float qv[4], kv[4];
#pragma unroll
            for (int i = 0; i < 4; i++) qv[i] = Qs[(ty * 4 + i) * APAD + d];
#pragma unroll
            for (int j = 0; j < 4; j++) kv[j] = Ks[(tx * 4 + j) * APAD + d];
#pragma unroll
            for (int i = 0; i < 4; i++)
#pragma unroll
                for (int j = 0; j < 4; j++)
                    s[i][j] = fmaf(qv[i], kv[j], s[i][j]);
        }
        const float scale = 0.125f;
#pragma unroll
        for (int i = 0; i < 4; i++)
#pragma unroll
            for (int j = 0; j < 4; j++) s[i][j] *= scale;

#pragma unroll
        for (int i = 0; i < 4; i++) {
            float t = s[i][0];
#pragma unroll
            for (int j = 1; j < 4; j++) t = fmaxf(t, s[i][j]);
            red[(ty * 4 + i) * 16 + tx] = t;
        }
        __syncthreads();
        if (tid < 64) {
            float mx = red[tid * 16];
#pragma unroll
            for (int t = 1; t < 16; t++) mx = fmaxf(mx, red[tid * 16 + t]);
            float mold = mrow[tid];
            float mnew = fmaxf(mold, mx);
            mrow[tid] = mnew;
            arow[tid] = __expf(mold - mnew);
        }
        __syncthreads();

        float a_i[4], m_i[4], psum[4];
#pragma unroll
        for (int i = 0; i < 4; i++) {
            a_i[i] = arow[ty * 4 + i];
            m_i[i] = mrow[ty * 4 + i];
            psum[i] = 0.f;
        }
#pragma unroll
        for (int i = 0; i < 4; i++) {
#pragma unroll
            for (int j = 0; j < 4; j++) {
                float p = __expf(s[i][j] - m_i[i]);
                Ks[(ty * 4 + i) * APAD + tx * 4 + j] = p;
                psum[i] += p;
                acc[i][j] *= a_i[i];
            }
            red[(ty * 4 + i) * 16 + tx] = psum[i];
        }
        __syncthreads();
        if (tid < 64) {
            float ssum = 0.f;
#pragma unroll
            for (int t = 0; t < 16; t++) ssum += red[tid * 16 + t];
            lrow[tid] = lrow[tid] * arow[tid] + ssum;
        }

        for (int kk = 0; kk < 64; kk++) {
            float pv[4], vv[4];
#pragma unroll
            for (int i = 0; i < 4; i++) pv[i] = Ks[(ty * 4 + i) * APAD + kk];
#pragma unroll
            for (int j = 0; j < 4; j++) vv[j] = Vs[kk * APAD + tx * 4 + j];
#pragma unroll
            for (int i = 0; i < 4; i++)
#pragma unroll
                for (int j = 0; j < 4; j++)
                    acc[i][j] = fmaf(pv[i], vv[j], acc[i][j]);
        }
    }
    __syncthreads();

#pragma unroll
    for (int i = 0; i < 4; i++) {
        const int r = ty * 4 + i;
        const float linv = 1.0f / lrow[r];
        const size_t o = ((size_t)b * S_ + q0 + r) * E_ + h * HD_ + tx * 4;
        __nv_bfloat162 h01, h23, l01, l23;
        float v0 = acc[i][0] * linv, v1 = acc[i][1] * linv;
        float v2 = acc[i][2] * linv, v3 = acc[i][3] * linv;
        split2(v0, h01.x, l01.x); split2(v1, h01.y, l01.y);
        split2(v2, h23.x, l23.x); split2(v3, h23.y, l23.y);
        *(__nv_bfloat162*)(ctxh + o)     = h01;
        *(__nv_bfloat162*)(ctxh + o + 2) = h23;
        *(__nv_bfloat162*)(ctxl + o)     = l01;
        *(__nv_bfloat162*)(ctxl + o + 2) = l23;
    }
}

// ============================================================================
// Fused residual-add + LayerNorm; optional bf16 hi/lo emission
// ============================================================================
template<int EMIT>
__global__ __launch_bounds__(256)
void add_ln_kernel(const float* __restrict__ x, const float* __restrict__ y,
                   const float* __restrict__ g, const float* __restrict__ beta,
                   float* __restrict__ out,
                   __nv_bfloat16* __restrict__ oh, __nv_bfloat16* __restrict__ ol) {
    __shared__ float red1[8], red2[8];
    __shared__ float s_mean, s_rstd;
    const int row = blockIdx.x;
    const int tid = threadIdx.x;

    const float4 xv = ((const float4*)(x + (size_t)row * E_))[tid];
    const float4 yv = ((const float4*)(y + (size_t)row * E_))[tid];
    float v0 = xv.x + yv.x, v1 = xv.y + yv.y, v2 = xv.z + yv.z, v3 = xv.w + yv.w;

    float s  = v0 + v1 + v2 + v3;
    float ss = v0 * v0 + v1 * v1 + v2 * v2 + v3 * v3;
#pragma unroll
    for (int o = 16; o > 0; o >>= 1) {
        s  += __shfl_down_sync(0xffffffffu, s, o);
        ss += __shfl_down_sync(0xffffffffu, ss, o);
    }
    const int warp = tid >> 5, lane = tid & 31;
    if (lane == 0) { red1[warp] = s; red2[warp] = ss; }
    __syncthreads();
    if (tid == 0) {
        float ts = 0.f, tss = 0.f;
#pragma unroll
        for (int w = 0; w < 8; w++) { ts += red1[w]; tss += red2[w]; }
        float mean = ts * (1.0f / E_);
        float var  = tss * (1.0f / E_) - mean * mean;
        s_mean = mean;
        s_rstd = rsqrtf(var + 1e-5f);
    }
    __syncthreads();
    const float mean = s_mean, rstd = s_rstd;

    const float4 gv = ((const float4*)g)[tid];
    const float4 bv = ((const float4*)beta)[tid];
    float4 o;
    o.x = (v0 - mean) * rstd * gv.x + bv.x;
    o.y = (v1 - mean) * rstd * gv.y + bv.y;
    o.z = (v2 - mean) * rstd * gv.z + bv.z;
    o.w = (v3 - mean) * rstd * gv.w + bv.w;
    ((float4*)(out + (size_t)row * E_))[tid] = o;
    if (EMIT) {
        __nv_bfloat162 h01, h23, l01, l23;
        split2(o.x, h01.x, l01.x); split2(o.y, h01.y, l01.y);
        split2(o.z, h23.x, l23.x); split2(o.w, h23.y, l23.y);
        const size_t off = (size_t)row * E_ + tid * 4;
        *(__nv_bfloat162*)(oh + off)     = h01;
        *(__nv_bfloat162*)(oh + off + 2) = h23;
        *(__nv_bfloat162*)(ol + off)     = l01;
        *(__nv_bfloat162*)(ol + off + 2) = l23;
    }
}

// ============================================================================
// Launch
// ============================================================================
extern "C" void kernel_launch(void* const* d_in, const int* in_sizes, int n_in,
                              void* d_out, int out_size) {
    const float* x     = (const float*)d_in[0];
    const float* w_qkv = (const float*)d_in[1];
    const float* b_qkv = (const float*)d_in[2];
    const float* w_out = (const float*)d_in[3];
    const float* b_out = (const float*)d_in[4];
    const float* g1    = (const float*)d_in[5];
    const float* beta1 = (const float*)d_in[6];
    const float* g2    = (const float*)d_in[7];
    const float* beta2 = (const float*)d_in[8];
    const float* w1    = (const float*)d_in[9];
    const float* bf1   = (const float*)d_in[10];
    const float* w2    = (const float*)d_in[11];
    const float* bf2   = (const float*)d_in[12];
    float* out = (float*)d_out;

    float *qkv, *tmp, *x1;
    cudaGetSymbolAddress((void**)&qkv,  g_qkv);
    cudaGetSymbolAddress((void**)&tmp,  g_tmp);
    cudaGetSymbolAddress((void**)&x1,   g_x1);

    __nv_bfloat16 *xh, *xl, *ctxh, *ctxl, *x1h, *x1l, *hh, *hl;
    __nv_bfloat16 *wqkvh, *wqkvl, *wouth, *woutl, *w1h, *w1l, *w2h, *w2l;
    cudaGetSymbolAddress((void**)&xh, g_xh);     cudaGetSymbolAddress((void**)&xl, g_xl);
    cudaGetSymbolAddress((void**)&ctxh, g_ctxh); cudaGetSymbolAddress((void**)&ctxl, g_ctxl);
    cudaGetSymbolAddress((void**)&x1h, g_x1h);   cudaGetSymbolAddress((void**)&x1l, g_x1l);
    cudaGetSymbolAddress((void**)&hh, g_hh);     cudaGetSymbolAddress((void**)&hl, g_hl);
    cudaGetSymbolAddress((void**)&wqkvh, g_wqkvh); cudaGetSymbolAddress((void**)&wqkvl, g_wqkvl);
    cudaGetSymbolAddress((void**)&wouth, g_wouth); cudaGetSymbolAddress((void**)&woutl, g_woutl);
    cudaGetSymbolAddress((void**)&w1h, g_w1h);   cudaGetSymbolAddress((void**)&w1l, g_w1l);
    cudaGetSymbolAddress((void**)&w2h, g_w2h);   cudaGetSymbolAddress((void**)&w2l, g_w2l);

    const int attn_smem = (3 * 64 * APAD + 64 * 16 + 3 * 64) * (int)sizeof(float);
    cudaFuncSetAttribute(attn_kernel, cudaFuncAttributeMaxDynamicSharedMemorySize, attn_smem);
    cudaFuncSetAttribute(mma_gemm<0,0>, cudaFuncAttributeMaxDynamicSharedMemorySize, GSMEM_TOTAL);
    cudaFuncSetAttribute(mma_gemm<1,1>, cudaFuncAttributeMaxDynamicSharedMemorySize, GSMEM_TOTAL);

    dim3 thr(256);
    auto split = [&](const float* s, __nv_bfloat16* h, __nv_bfloat16* l, size_t n) {
        int n4 = (int)(n / 4);
        split_kernel<<<(n4 + 255) / 256, 256>>>(s, h, l, n4);
    };

    // weight + input splits
    split(w_qkv, wqkvh, wqkvl, (size_t)3 * E_ * E_);
    split(w_out, wouth, woutl, (size_t)E_ * E_);
    split(w1,    w1h,   w1l,   (size_t)FF_ * E_);
    split(w2,    w2h,   w2l,   (size_t)E_ * FF_);
    split(x, xh, xl, (size_t)M_ * E_);

    // 1) qkv = x @ w_qkv^T + b_qkv   (fp32 out)
    mma_gemm<0,0><<<dim3(3 * E_ / 128, M_ / 128), thr, GSMEM_TOTAL>>>(
        xh, xl, wqkvh, wqkvl, b_qkv, qkv, nullptr, nullptr, M_, 3 * E_, E_);

    // 2) flash attention -> ctx (bf16 hi/lo)
    attn_kernel<<<dim3(S_ / 64, H_, B_), thr, attn_smem>>>(qkv, ctxh, ctxl);

    // 3) out-proj (fp32) + residual LN -> x1 (+ hi/lo)
    mma_gemm<0,0><<<dim3(E_ / 128, M_ / 128), thr, GSMEM_TOTAL>>>(
        ctxh, ctxl, wouth, woutl, b_out, tmp, nullptr, nullptr, M_, E_, E_);
    add_ln_kernel<1><<<M_, thr>>>(x, tmp, g1, beta1, x1, x1h, x1l);

    // 4) h = gelu(x1 @ w1^T + bf1) -> bf16 hi/lo directly
    mma_gemm<1,1><<<dim3(FF_ / 128, M_ / 128), thr, GSMEM_TOTAL>>>(
        x1h, x1l, w1h, w1l, bf1, nullptr, hh, hl, M_, FF_, E_);

    // 5) ffn2 (fp32) + residual LN -> out
    mma_gemm<0,0><<<dim3(E_ / 128, M_ / 128), thr, GSMEM_TOTAL>>>(
        hh, hl, w2h, w2l, bf2, tmp, nullptr, nullptr, M_, E_, FF_);
    add_ln_kernel<0><<<M_, thr>>>(x1, tmp, g2, beta2, out, nullptr, nullptr);
}

// round 5
// speedup vs baseline: 1.7733x; 1.0986x over previous
#include <cuda_runtime.h>
#include <cuda_fp16.h>
#include <math.h>
#include <stdint.h>

// ---------------- problem constants ----------------
#define B_  2
#define S_  2048
#define E_  1024
#define H_  16
#define HD_ 64
#define FF_ 4096
#define M_  (B_ * S_)          // 4096 rows

// ---------------- fp32 scratch ----------------
__device__ __align__(128) float g_qkv[(size_t)M_ * 3 * E_];
__device__ __align__(128) float g_tmp[(size_t)M_ * E_];
__device__ __align__(128) float g_x1 [(size_t)M_ * E_];

// ---------------- fp16 scratch ----------------
__device__ __align__(128) __half g_xh  [(size_t)M_ * E_],  g_xl  [(size_t)M_ * E_];
__device__ __align__(128) __half g_ctxh[(size_t)M_ * E_],  g_ctxl[(size_t)M_ * E_];
__device__ __align__(128) __half g_x1h [(size_t)M_ * E_],  g_x1l [(size_t)M_ * E_];
__device__ __align__(128) __half g_hh  [(size_t)M_ * FF_], g_hl  [(size_t)M_ * FF_];
__device__ __align__(128) __half g_wqkvh[(size_t)3 * E_ * E_];
__device__ __align__(128) __half g_wouth[(size_t)E_ * E_];
__device__ __align__(128) __half g_w1h  [(size_t)FF_ * E_];
__device__ __align__(128) __half g_w2h  [(size_t)E_ * FF_];

// ============================================================================
// helpers
// ============================================================================
__device__ __forceinline__ uint32_t smem_u32(const void* p) {
    uint32_t a;
    asm("{ .reg .u64 t; cvta.to.shared.u64 t, %1; cvt.u32.u64 %0, t; }"
        : "=r"(a) : "l"(p));
    return a;
}

__device__ __forceinline__ void cp16(uint32_t dst, const void* src) {
    asm volatile("cp.async.cg.shared.global [%0], [%1], 16;"
                 :: "r"(dst), "l"(src) : "memory");
}
#define CP_COMMIT()  asm volatile("cp.async.commit_group;" ::: "memory")
#define CP_WAIT(N)   asm volatile("cp.async.wait_group %0;" :: "n"(N) : "memory")

__device__ __forceinline__ void ldsm4(uint32_t* r, uint32_t addr) {
    asm volatile("ldmatrix.sync.aligned.m8n8.x4.shared.b16 {%0,%1,%2,%3}, [%4];"
                 : "=r"(r[0]), "=r"(r[1]), "=r"(r[2]), "=r"(r[3]) : "r"(addr));
}

__device__ __forceinline__ void mma16816(float d[4], const uint32_t a[4],
                                         uint32_t b0, uint32_t b1) {
    asm volatile(
        "mma.sync.aligned.m16n8k16.row.col.f32.f16.f16.f32 "
        "{%0,%1,%2,%3}, {%4,%5,%6,%7}, {%8,%9}, {%0,%1,%2,%3};"
        : "+f"(d[0]), "+f"(d[1]), "+f"(d[2]), "+f"(d[3])
        : "r"(a[0]), "r"(a[1]), "r"(a[2]), "r"(a[3]), "r"(b0), "r"(b1));
}

__device__ __forceinline__ void split2h(float v, __half& h, __half& l) {
    h = __float2half_rn(v);
    l = __float2half_rn(v - __half2float(h));
}

// ============================================================================
// Fused weight convert: fp32 -> fp16 (single), 4 weights in one launch.
// Block ranges: wqkv 3072, wout 1024, w1 4096, w2 4096  (256 thr, float4 each)
// ============================================================================
__global__ __launch_bounds__(256)
void wconv_kernel(const float* __restrict__ s0, const float* __restrict__ s1,
                  const float* __restrict__ s2, const float* __restrict__ s3,
                  __half* __restrict__ d0, __half* __restrict__ d1,
                  __half* __restrict__ d2, __half* __restrict__ d3) {
    const int b = blockIdx.x;
    const float* s; __half* d; int base;
    if      (b < 3072) { s = s0; d = d0; base = b; }
    else if (b < 4096) { s = s1; d = d1; base = b - 3072; }
    else if (b < 8192) { s = s2; d = d2; base = b - 4096; }
    else               { s = s3; d = d3; base = b - 8192; }
    const int i = base * 256 + threadIdx.x;
    float4 v = ((const float4*)s)[i];
    ((__half2*)d)[2 * i]     = __floats2half2_rn(v.x, v.y);
    ((__half2*)d)[2 * i + 1] = __floats2half2_rn(v.z, v.w);
}

// ============================================================================
// Split fp32 -> (fp16 hi, fp16 lo)
// ============================================================================
__global__ __launch_bounds__(256)
void split_kernel(const float* __restrict__ src, __half* __restrict__ hi,
                  __half* __restrict__ lo, int n4) {
    int i = blockIdx.x * 256 + threadIdx.x;
    if (i >= n4) return;
    float4 v = ((const float4*)src)[i];
    __half2 h01, h23, l01, l23;
    split2h(v.x, h01.x, l01.x); split2h(v.y, h01.y, l01.y);
    split2h(v.z, h23.x, l23.x); split2h(v.w, h23.y, l23.y);
    ((__half2*)hi)[2 * i]     = h01;
    ((__half2*)hi)[2 * i + 1] = h23;
    ((__half2*)lo)[2 * i]     = l01;
    ((__half2*)lo)[2 * i + 1] = l23;
}

// ============================================================================
// mma.sync GEMM: C = (Ah+Al)[M,K] @ B[N,K]^T + bias   (fp16 2-term split)
// CTA 128x128, K-tile 32, 8 warps (2Mx4N), warp tile 64x32, 4-stage cp.async.
// ACT: 0 none / 1 exact GELU.  OUT: 0 fp32 / 1 fp16 hi+lo.
// ============================================================================
#define PAD   40                          // fp16 per smem row (32 data + 8 pad)
#define TILE_BYTES (128 * PAD * 2)        // 10240
#define STAGE_BYTES (3 * TILE_BYTES)      // Ah, Al, B
#define NSTAGE 4
#define GSMEM_TOTAL (NSTAGE * STAGE_BYTES)  // 122880

template<int ACT, int OUT>
__global__ __launch_bounds__(256, 1)
void mma_gemm(const __half* __restrict__ Ah, const __half* __restrict__ Al,
              const __half* __restrict__ Bh,
              const float* __restrict__ bias,
              float* __restrict__ C,
              __half* __restrict__ Ch, __half* __restrict__ Cl,
              int M, int N, int K) {
    extern __shared__ char smem[];
    const uint32_t sbase = smem_u32(smem);
    const int tid  = threadIdx.x;
    const int bm   = blockIdx.y * 128;
    const int bn   = blockIdx.x * 128;

    const int wid  = tid >> 5;
    const int lane = tid & 31;
    const int wm   = (wid & 1) * 64;
    const int wn   = (wid >> 1) * 32;
    const int g    = lane >> 3;
    const int rig  = lane & 7;

    const __half* srcA_h = Ah + (size_t)bm * K;
    const __half* srcA_l = Al + (size_t)bm * K;
    const __half* srcB   = Bh + (size_t)bn * K;

    float acc[4][4][4];
#pragma unroll
    for (int i = 0; i < 4; i++)
#pragma unroll
        for (int j = 0; j < 4; j++)
#pragma unroll
            for (int r = 0; r < 4; r++) acc[i][j][r] = 0.f;

    const int nt = K >> 5;

    const int lrow = tid >> 2;        // 0..63 (+64 on second half)
    const int lc4  = (tid & 3);

    auto load_stage = [&](int kt, int st) {
        const uint32_t sdst = sbase + st * STAGE_BYTES;
        const size_t koff = (size_t)kt * 32 + lc4 * 8;
        const uint32_t so = lc4 * 16;
#pragma unroll
        for (int half_ = 0; half_ < 2; half_++) {
            const int row = lrow + half_ * 64;
            const uint32_t rowo = row * PAD * 2 + so;
            const size_t gof = (size_t)row * K + koff;
            cp16(sdst + 0 * TILE_BYTES + rowo, srcA_h + gof);
            cp16(sdst + 1 * TILE_BYTES + rowo, srcA_l + gof);
            cp16(sdst + 2 * TILE_BYTES + rowo, srcB   + gof);
        }
    };

    load_stage(0, 0); CP_COMMIT();
    load_stage(1, 1); CP_COMMIT();
    load_stage(2, 2); CP_COMMIT();

    const uint32_t aoff = ((wm + (g & 1) * 8 + rig) * PAD + (g >> 1) * 8) * 2;
    const uint32_t boff = ((wn + (g >> 1) * 8 + rig) * PAD + (g & 1) * 8) * 2;

    for (int kt = 0; kt < nt; kt++) {
        CP_WAIT(2);
        __syncthreads();
        if (kt + 3 < nt) load_stage(kt + 3, (kt + 3) & (NSTAGE - 1));
        CP_COMMIT();

        const uint32_t st  = sbase + (kt & (NSTAGE - 1)) * STAGE_BYTES;
        const uint32_t sAh = st;
        const uint32_t sAl = st + TILE_BYTES;
        const uint32_t sB  = st + 2 * TILE_BYTES;

#pragma unroll
        for (int ks = 0; ks < 2; ks++) {
            const uint32_t ko = ks * 32;
            uint32_t a0[4][4], a1[4][4], b0[2][4];
#pragma unroll
            for (int i = 0; i < 4; i++) ldsm4(a0[i], sAh + aoff + ko + i * 16 * PAD * 2);
#pragma unroll
            for (int j2 = 0; j2 < 2; j2++) ldsm4(b0[j2], sB + boff + ko + j2 * 16 * PAD * 2);
#pragma unroll
            for (int i = 0; i < 4; i++)
#pragma unroll
                for (int j = 0; j < 4; j++)
                    mma16816(acc[i][j], a0[i], b0[j >> 1][(j & 1) * 2], b0[j >> 1][(j & 1) * 2 + 1]);
#pragma unroll
            for (int i = 0; i < 4; i++) ldsm4(a1[i], sAl + aoff + ko + i * 16 * PAD * 2);
#pragma unroll
            for (int i = 0; i < 4; i++)
#pragma unroll
                for (int j = 0; j < 4; j++)
                    mma16816(acc[i][j], a1[i], b0[j >> 1][(j & 1) * 2], b0[j >> 1][(j & 1) * 2 + 1]);
        }
        __syncthreads();
    }

    // epilogue
    const int m_l = lane >> 2;
    const int n_l = (lane & 3) * 2;
#pragma unroll
    for (int j = 0; j < 4; j++) {
        const int n = bn + wn + j * 8 + n_l;
        const float2 b2 = *(const float2*)(bias + n);
#pragma unroll
        for (int i = 0; i < 4; i++) {
            const int m = bm + wm + i * 16 + m_l;
            float v[4];
            v[0] = acc[i][j][0] + b2.x;
            v[1] = acc[i][j][1] + b2.y;
            v[2] = acc[i][j][2] + b2.x;
            v[3] = acc[i][j][3] + b2.y;
            if (ACT == 1) {
#pragma unroll
                for (int r = 0; r < 4; r++)
                    v[r] = 0.5f * v[r] * (1.0f + erff(v[r] * 0.70710678118654752f));
            }
            if (OUT == 0) {
                float2 o0; o0.x = v[0]; o0.y = v[1];
                float2 o1; o1.x = v[2]; o1.y = v[3];
                *(float2*)(C + (size_t)m * N + n)       = o0;
                *(float2*)(C + (size_t)(m + 8) * N + n) = o1;
            } else {
                __half2 h0, l0, h1, l1;
                split2h(v[0], h0.x, l0.x); split2h(v[1], h0.y, l0.y);
                split2h(v[2], h1.x, l1.x); split2h(v[3], h1.y, l1.y);
                *(__half2*)(Ch + (size_t)m * N + n)       = h0;
                *(__half2*)(Cl + (size_t)m * N + n)       = l0;
                *(__half2*)(Ch + (size_t)(m + 8) * N + n) = h1;
                *(__half2*)(Cl + (size_t)(m + 8) * N + n) = l1;
            }
        }
    }
}

// ============================================================================
// Flash attention (fp32 CUDA-core) -> emits ctx as fp16 hi/lo
// ============================================================================
#define APAD 68

__global__ __launch_bounds__(256)
void attn_kernel(const float* __restrict__ qkv,
                 __half* __restrict__ ctxh, __half* __restrict__ ctxl) {
    extern __shared__ float sm[];
    float* Qs  = sm;
    float* Ks  = Qs  + 64 * APAD;
    float* Vs  = Ks  + 64 * APAD;
    float* red = Vs  + 64 * APAD;
    float* mrow = red + 64 * 16;
    float* lrow = mrow + 64;
    float* arow = lrow + 64;

    const int q0 = blockIdx.x * 64;
    const int h  = blockIdx.y;
    const int b  = blockIdx.z;
    const int tid = threadIdx.x;
    const int tx = tid & 15;
    const int ty = tid >> 4;

    const int LD = 3 * E_;
    const float* base = qkv + (size_t)b * S_ * LD + h * (3 * HD_);

    {
        const int r  = tid >> 2;
        const int c0 = (tid & 3) * 16;
        const float* src = base + (size_t)(q0 + r) * LD + c0;
        float* dst = Qs + r * APAD + c0;
#pragma unroll
        for (int j = 0; j < 16; j += 4)
            *(float4*)(dst + j) = *(const float4*)(src + j);
    }
    if (tid < 64) { mrow[tid] = -1e30f; lrow[tid] = 0.f; }

    float acc[4][4];
#pragma unroll
    for (int i = 0; i < 4; i++)
#pragma unroll
        for (int j = 0; j < 4; j++) acc[i][j] = 0.f;

    for (int kt = 0; kt < S_ / 64; kt++) {
        const int k0 = kt * 64;
        __syncthreads();
        {
            const int r  = tid >> 2;
            const int c0 = (tid & 3) * 16;
            const float* srck = base + (size_t)(k0 + r) * LD + HD_ + c0;
            const float* srcv = base + (size_t)(k0 + r) * LD + 2 * HD_ + c0;
            float* dk = Ks + r * APAD + c0;
            float* dv = Vs + r * APAD + c0;
#pragma unroll
            for (int j = 0; j < 16; j += 4) {
                *(float4*)(dk + j) = *(const float4*)(srck + j);
                *(float4*)(dv + j) = *(const float4*)(srcv + j);
            }
        }
        __syncthreads();

        float s[4][4];
#pragma unroll
        for (int i = 0; i < 4; i++)
#pragma unroll
            for (int j = 0; j < 4; j++) s[i][j] = 0.f;

        for (int d = 0; d < 64; d++) {
            float qv[4], kv[4];
#pragma unroll
            for (int i = 0; i < 4; i++) qv[i] = Qs[(ty * 4 + i) * APAD + d];
#pragma unroll
            for (int j = 0; j < 4; j++) kv[j] = Ks[(tx * 4 + j) * APAD + d];
#pragma unroll
            for (int i = 0; i < 4; i++)
#pragma unroll
                for (int j = 0; j < 4; j++)
                    s[i][j] = fmaf(qv[i], kv[j], s[i][j]);
        }
        const float scale = 0.125f;
#pragma unroll
        for (int i = 0; i < 4; i++)
#pragma unroll
            for (int j = 0; j < 4; j++) s[i][j] *= scale;

#pragma unroll
        for (int i = 0; i < 4; i++) {
            float t = s[i][0];
#pragma unroll
            for (int j = 1; j < 4; j++) t = fmaxf(t, s[i][j]);
            red[(ty * 4 + i) * 16 + tx] = t;
        }
        __syncthreads();
        if (tid < 64) {
            float mx = red[tid * 16];
#pragma unroll
            for (int t = 1; t < 16; t++) mx = fmaxf(mx, red[tid * 16 + t]);
            float mold = mrow[tid];
            float mnew = fmaxf(mold, mx);
            mrow[tid] = mnew;
            arow[tid] = __expf(mold - mnew);
        }
        __syncthreads();

        float a_i[4], m_i[4], psum[4];
#pragma unroll
        for (int i = 0; i < 4; i++) {
            a_i[i] = arow[ty * 4 + i];
            m_i[i] = mrow[ty * 4 + i];
            psum[i] = 0.f;
        }
#pragma unroll
        for (int i = 0; i < 4; i++) {
#pragma unroll
            for (int j = 0; j < 4; j++) {
                float p = __expf(s[i][j] - m_i[i]);
                Ks[(ty * 4 + i) * APAD + tx * 4 + j] = p;
                psum[i] += p;
                acc[i][j] *= a_i[i];
            }
            red[(ty * 4 + i) * 16 + tx] = psum[i];
        }
        __syncthreads();
        if (tid < 64) {
            float ssum = 0.f;
#pragma unroll
            for (int t = 0; t < 16; t++) ssum += red[tid * 16 + t];
            lrow[tid] = lrow[tid] * arow[tid] + ssum;
        }

        for (int kk = 0; kk < 64; kk++) {
            float pv[4], vv[4];
#pragma unroll
            for (int i = 0; i < 4; i++) pv[i] = Ks[(ty * 4 + i) * APAD + kk];
#pragma unroll
            for (int j = 0; j < 4; j++) vv[j] = Vs[kk * APAD + tx * 4 + j];
#pragma unroll
            for (int i = 0; i < 4; i++)
#pragma unroll
                for (int j = 0; j < 4; j++)
                    acc[i][j] = fmaf(pv[i], vv[j], acc[i][j]);
        }
    }
    __syncthreads();

#pragma unroll
    for (int i = 0; i < 4; i++) {
        const int r = ty * 4 + i;
        const float linv = 1.0f / lrow[r];
        const size_t o = ((size_t)b * S_ + q0 + r) * E_ + h * HD_ + tx * 4;
        __half2 h01, h23, l01, l23;
        float v0 = acc[i][0] * linv, v1 = acc[i][1] * linv;
        float v2 = acc[i][2] * linv, v3 = acc[i][3] * linv;
        split2h(v0, h01.x, l01.x); split2h(v1, h01.y, l01.y);
        split2h(v2, h23.x, l23.x); split2h(v3, h23.y, l23.y);
        *(__half2*)(ctxh + o)     = h01;
        *(__half2*)(ctxh + o + 2) = h23;
        *(__half2*)(ctxl + o)     = l01;
        *(__half2*)(ctxl + o + 2) = l23;
    }
}

// ============================================================================
// Fused residual-add + LayerNorm; optional fp16 hi/lo emission
// ============================================================================
template<int EMIT>
__global__ __launch_bounds__(256)
void add_ln_kernel(const float* __restrict__ x, const float* __restrict__ y,
                   const float* __restrict__ g, const float* __restrict__ beta,
                   float* __restrict__ out,
                   __half* __restrict__ oh, __half* __restrict__ ol) {
    __shared__ float red1[8], red2[8];
    __shared__ float s_mean, s_rstd;
    const int row = blockIdx.x;
    const int tid = threadIdx.x;

    const float4 xv = ((const float4*)(x + (size_t)row * E_))[tid];
    const float4 yv = ((const float4*)(y + (size_t)row * E_))[tid];
    float v0 = xv.x + yv.x, v1 = xv.y + yv.y, v2 = xv.z + yv.z, v3 = xv.w + yv.w;

    float s  = v0 + v1 + v2 + v3;
    float ss = v0 * v0 + v1 * v1 + v2 * v2 + v3 * v3;
#pragma unroll
    for (int o = 16; o > 0; o >>= 1) {
        s  += __shfl_down_sync(0xffffffffu, s, o);
        ss += __shfl_down_sync(0xffffffffu, ss, o);
    }
    const int warp = tid >> 5, lane = tid & 31;
    if (lane == 0) { red1[warp] = s; red2[warp] = ss; }
    __syncthreads();
    if (tid == 0) {
        float ts = 0.f, tss = 0.f;
#pragma unroll
        for (int w = 0; w < 8; w++) { ts += red1[w]; tss += red2[w]; }
        float mean = ts * (1.0f / E_);
        float var  = tss * (1.0f / E_) - mean * mean;
        s_mean = mean;
        s_rstd = rsqrtf(var + 1e-5f);
    }
    __syncthreads();
    const float mean = s_mean, rstd = s_rstd;

    const float4 gv = ((const float4*)g)[tid];
    const float4 bv = ((const float4*)beta)[tid];
    float4 o;
    o.x = (v0 - mean) * rstd * gv.x + bv.x;
    o.y = (v1 - mean) * rstd * gv.y + bv.y;
    o.z = (v2 - mean) * rstd * gv.z + bv.z;
    o.w = (v3 - mean) * rstd * gv.w + bv.w;
    ((float4*)(out + (size_t)row * E_))[tid] = o;
    if (EMIT) {
        __half2 h01, h23, l01, l23;
        split2h(o.x, h01.x, l01.x); split2h(o.y, h01.y, l01.y);
        split2h(o.z, h23.x, l23.x); split2h(o.w, h23.y, l23.y);
        const size_t off = (size_t)row * E_ + tid * 4;
        *(__half2*)(oh + off)     = h01;
        *(__half2*)(oh + off + 2) = h23;
        *(__half2*)(ol + off)     = l01;
        *(__half2*)(ol + off + 2) = l23;
    }
}

// ============================================================================
// Launch
// ============================================================================
extern "C" void kernel_launch(void* const* d_in, const int* in_sizes, int n_in,
                              void* d_out, int out_size) {
    const float* x     = (const float*)d_in[0];
    const float* w_qkv = (const float*)d_in[1];
    const float* b_qkv = (const float*)d_in[2];
    const float* w_out = (const float*)d_in[3];
    const float* b_out = (const float*)d_in[4];
    const float* g1    = (const float*)d_in[5];
    const float* beta1 = (const float*)d_in[6];
    const float* g2    = (const float*)d_in[7];
    const float* beta2 = (const float*)d_in[8];
    const float* w1    = (const float*)d_in[9];
    const float* bf1   = (const float*)d_in[10];
    const float* w2    = (const float*)d_in[11];
    const float* bf2   = (const float*)d_in[12];
    float* out = (float*)d_out;

    float *qkv, *tmp, *x1;
    cudaGetSymbolAddress((void**)&qkv,  g_qkv);
    cudaGetSymbolAddress((void**)&tmp,  g_tmp);
    cudaGetSymbolAddress((void**)&x1,   g_x1);

    __half *xh, *xl, *ctxh, *ctxl, *x1h, *x1l, *hh, *hl;
    __half *wqkvh, *wouth, *w1h, *w2h;
    cudaGetSymbolAddress((void**)&xh, g_xh);     cudaGetSymbolAddress((void**)&xl, g_xl);
    cudaGetSymbolAddress((void**)&ctxh, g_ctxh); cudaGetSymbolAddress((void**)&ctxl, g_ctxl);
    cudaGetSymbolAddress((void**)&x1h, g_x1h);   cudaGetSymbolAddress((void**)&x1l, g_x1l);
    cudaGetSymbolAddress((void**)&hh, g_hh);     cudaGetSymbolAddress((void**)&hl, g_hl);
    cudaGetSymbolAddress((void**)&wqkvh, g_wqkvh);
    cudaGetSymbolAddress((void**)&wouth, g_wouth);
    cudaGetSymbolAddress((void**)&w1h, g_w1h);
    cudaGetSymbolAddress((void**)&w2h, g_w2h);

    const int attn_smem = (3 * 64 * APAD + 64 * 16 + 3 * 64) * (int)sizeof(float);
    cudaFuncSetAttribute(attn_kernel, cudaFuncAttributeMaxDynamicSharedMemorySize, attn_smem);
    cudaFuncSetAttribute(mma_gemm<0,0>, cudaFuncAttributeMaxDynamicSharedMemorySize, GSMEM_TOTAL);
    cudaFuncSetAttribute(mma_gemm<1,1>, cudaFuncAttributeMaxDynamicSharedMemorySize, GSMEM_TOTAL);

    dim3 thr(256);

    // launch 0: fused weight convert (fp32 -> fp16)
    wconv_kernel<<<12288, thr>>>(w_qkv, w_out, w1, w2, wqkvh, wouth, w1h, w2h);

    // launch 1: x split (fp16 hi/lo)
    split_kernel<<<(M_ * E_ / 4 + 255) / 256, 256>>>(x, xh, xl, M_ * E_ / 4);

    // launch 2: qkv = x @ w_qkv^T + b_qkv (fp32 out)
    mma_gemm<0,0><<<dim3(3 * E_ / 128, M_ / 128), thr, GSMEM_TOTAL>>>(
        xh, xl, wqkvh, b_qkv, qkv, nullptr, nullptr, M_, 3 * E_, E_);

    // launch 3: flash attention -> ctx (fp16 hi/lo)
    attn_kernel<<<dim3(S_ / 64, H_, B_), thr, attn_smem>>>(qkv, ctxh, ctxl);

    // launch 4 (ncu capture slot): out-proj (fp32 out)
    mma_gemm<0,0><<<dim3(E_ / 128, M_ / 128), thr, GSMEM_TOTAL>>>(
        ctxh, ctxl, wouth, b_out, tmp, nullptr, nullptr, M_, E_, E_);

    // launch 5: residual + LN -> x1 (+ fp16 hi/lo)
    add_ln_kernel<1><<<M_, thr>>>(x, tmp, g1, beta1, x1, x1h, x1l);

    // launch 6: h = gelu(x1 @ w1^T + bf1) -> fp16 hi/lo directly
    mma_gemm<1,1><<<dim3(FF_ / 128, M_ / 128), thr, GSMEM_TOTAL>>>(
        x1h, x1l, w1h, bf1, nullptr, hh, hl, M_, FF_, E_);

    // launch 7: ffn2 (fp32 out)
    mma_gemm<0,0><<<dim3(E_ / 128, M_ / 128), thr, GSMEM_TOTAL>>>(
        hh, hl, w2h, bf2, tmp, nullptr, nullptr, M_, E_, FF_);

    // launch 8: residual + LN -> out
    add_ln_kernel<0><<<M_, thr>>>(x1, tmp, g2, beta2, out, nullptr, nullptr);
}

// round 6
// speedup vs baseline: 5.1293x; 2.8925x over previous
#include <cuda_runtime.h>
#include <cuda_fp16.h>
#include <math.h>
#include <stdint.h>

// ---------------- problem constants ----------------
#define B_  2
#define S_  2048
#define E_  1024
#define H_  16
#define HD_ 64
#define FF_ 4096
#define M_  (B_ * S_)          // 4096 rows

// ---------------- fp32 scratch ----------------
__device__ __align__(128) float g_tmp[(size_t)M_ * E_];
__device__ __align__(128) float g_x1 [(size_t)M_ * E_];

// ---------------- fp16 scratch ----------------
__device__ __align__(128) __half g_xh   [(size_t)M_ * E_],     g_xl   [(size_t)M_ * E_];
__device__ __align__(128) __half g_qkvh [(size_t)M_ * 3 * E_], g_qkvl [(size_t)M_ * 3 * E_];
__device__ __align__(128) __half g_ctxh [(size_t)M_ * E_],     g_ctxl [(size_t)M_ * E_];
__device__ __align__(128) __half g_x1h  [(size_t)M_ * E_],     g_x1l  [(size_t)M_ * E_];
__device__ __align__(128) __half g_hh   [(size_t)M_ * FF_],    g_hl   [(size_t)M_ * FF_];
__device__ __align__(128) __half g_wqkvh[(size_t)3 * E_ * E_];
__device__ __align__(128) __half g_wouth[(size_t)E_ * E_];
__device__ __align__(128) __half g_w1h  [(size_t)FF_ * E_];
__device__ __align__(128) __half g_w2h  [(size_t)E_ * FF_];

// ============================================================================
// helpers
// ============================================================================
__device__ __forceinline__ uint32_t smem_u32(const void* p) {
    uint32_t a;
    asm("{ .reg .u64 t; cvta.to.shared.u64 t, %1; cvt.u32.u64 %0, t; }"
        : "=r"(a) : "l"(p));
    return a;
}

__device__ __forceinline__ void cp16(uint32_t dst, const void* src) {
    asm volatile("cp.async.cg.shared.global [%0], [%1], 16;"
                 :: "r"(dst), "l"(src) : "memory");
}
#define CP_COMMIT()  asm volatile("cp.async.commit_group;" ::: "memory")
#define CP_WAIT(N)   asm volatile("cp.async.wait_group %0;" :: "n"(N) : "memory")

__device__ __forceinline__ void ldsm4(uint32_t* r, uint32_t addr) {
    asm volatile("ldmatrix.sync.aligned.m8n8.x4.shared.b16 {%0,%1,%2,%3}, [%4];"
                 : "=r"(r[0]), "=r"(r[1]), "=r"(r[2]), "=r"(r[3]) : "r"(addr));
}
__device__ __forceinline__ void ldsm4t(uint32_t* r, uint32_t addr) {
    asm volatile("ldmatrix.sync.aligned.m8n8.x4.trans.shared.b16 {%0,%1,%2,%3}, [%4];"
                 : "=r"(r[0]), "=r"(r[1]), "=r"(r[2]), "=r"(r[3]) : "r"(addr));
}

__device__ __forceinline__ void mma16816(float d[4], const uint32_t a[4],
                                         uint32_t b0, uint32_t b1) {
    asm volatile(
        "mma.sync.aligned.m16n8k16.row.col.f32.f16.f16.f32 "
        "{%0,%1,%2,%3}, {%4,%5,%6,%7}, {%8,%9}, {%0,%1,%2,%3};"
        : "+f"(d[0]), "+f"(d[1]), "+f"(d[2]), "+f"(d[3])
        : "r"(a[0]), "r"(a[1]), "r"(a[2]), "r"(a[3]), "r"(b0), "r"(b1));
}

__device__ __forceinline__ void split2h(float v, __half& h, __half& l) {
    h = __float2half_rn(v);
    l = __float2half_rn(v - __half2float(h));
}
__device__ __forceinline__ uint32_t packh2(__half a, __half b) {
    __half2 t; t.x = a; t.y = b;
    return *(uint32_t*)&t;
}

// ============================================================================
// Fused weight convert: fp32 -> fp16
// ============================================================================
__global__ __launch_bounds__(256)
void wconv_kernel(const float* __restrict__ s0, const float* __restrict__ s1,
                  const float* __restrict__ s2, const float* __restrict__ s3,
                  __half* __restrict__ d0, __half* __restrict__ d1,
                  __half* __restrict__ d2, __half* __restrict__ d3) {
    const int b = blockIdx.x;
    const float* s; __half* d; int base;
    if      (b < 3072) { s = s0; d = d0; base = b; }
    else if (b < 4096) { s = s1; d = d1; base = b - 3072; }
    else if (b < 8192) { s = s2; d = d2; base = b - 4096; }
    else               { s = s3; d = d3; base = b - 8192; }
    const int i = base * 256 + threadIdx.x;
    float4 v = ((const float4*)s)[i];
    ((__half2*)d)[2 * i]     = __floats2half2_rn(v.x, v.y);
    ((__half2*)d)[2 * i + 1] = __floats2half2_rn(v.z, v.w);
}

// ============================================================================
// Split fp32 -> (fp16 hi, fp16 lo)
// ============================================================================
__global__ __launch_bounds__(256)
void split_kernel(const float* __restrict__ src, __half* __restrict__ hi,
                  __half* __restrict__ lo, int n4) {
    int i = blockIdx.x * 256 + threadIdx.x;
    if (i >= n4) return;
    float4 v = ((const float4*)src)[i];
    __half2 h01, h23, l01, l23;
    split2h(v.x, h01.x, l01.x); split2h(v.y, h01.y, l01.y);
    split2h(v.z, h23.x, l23.x); split2h(v.w, h23.y, l23.y);
    ((__half2*)hi)[2 * i]     = h01;
    ((__half2*)hi)[2 * i + 1] = h23;
    ((__half2*)lo)[2 * i]     = l01;
    ((__half2*)lo)[2 * i + 1] = l23;
}

// ============================================================================
// mma.sync GEMM (unchanged from R5): C = (Ah+Al) @ B^T + bias
// ============================================================================
#define PAD   40
#define TILE_BYTES (128 * PAD * 2)
#define STAGE_BYTES (3 * TILE_BYTES)
#define NSTAGE 4
#define GSMEM_TOTAL (NSTAGE * STAGE_BYTES)

template<int ACT, int OUT>
__global__ __launch_bounds__(256, 1)
void mma_gemm(const __half* __restrict__ Ah, const __half* __restrict__ Al,
              const __half* __restrict__ Bh,
              const float* __restrict__ bias,
              float* __restrict__ C,
              __half* __restrict__ Ch, __half* __restrict__ Cl,
              int M, int N, int K) {
    extern __shared__ char smem[];
    const uint32_t sbase = smem_u32(smem);
    const int tid  = threadIdx.x;
    const int bm   = blockIdx.y * 128;
    const int bn   = blockIdx.x * 128;

    const int wid  = tid >> 5;
    const int lane = tid & 31;
    const int wm   = (wid & 1) * 64;
    const int wn   = (wid >> 1) * 32;
    const int g    = lane >> 3;
    const int rig  = lane & 7;

    const __half* srcA_h = Ah + (size_t)bm * K;
    const __half* srcA_l = Al + (size_t)bm * K;
    const __half* srcB   = Bh + (size_t)bn * K;

    float acc[4][4][4];
#pragma unroll
    for (int i = 0; i < 4; i++)
#pragma unroll
        for (int j = 0; j < 4; j++)
#pragma unroll
            for (int r = 0; r < 4; r++) acc[i][j][r] = 0.f;

    const int nt = K >> 5;
    const int lrow = tid >> 2;
    const int lc4  = (tid & 3);

    auto load_stage = [&](int kt, int st) {
        const uint32_t sdst = sbase + st * STAGE_BYTES;
        const size_t koff = (size_t)kt * 32 + lc4 * 8;
        const uint32_t so = lc4 * 16;
#pragma unroll
        for (int half_ = 0; half_ < 2; half_++) {
            const int row = lrow + half_ * 64;
            const uint32_t rowo = row * PAD * 2 + so;
            const size_t gof = (size_t)row * K + koff;
            cp16(sdst + 0 * TILE_BYTES + rowo, srcA_h + gof);
            cp16(sdst + 1 * TILE_BYTES + rowo, srcA_l + gof);
            cp16(sdst + 2 * TILE_BYTES + rowo, srcB   + gof);
        }
    };

    load_stage(0, 0); CP_COMMIT();
    load_stage(1, 1); CP_COMMIT();
    load_stage(2, 2); CP_COMMIT();

    const uint32_t aoff = ((wm + (g & 1) * 8 + rig) * PAD + (g >> 1) * 8) * 2;
    const uint32_t boff = ((wn + (g >> 1) * 8 + rig) * PAD + (g & 1) * 8) * 2;

    for (int kt = 0; kt < nt; kt++) {
        CP_WAIT(2);
        __syncthreads();
        if (kt + 3 < nt) load_stage(kt + 3, (kt + 3) & (NSTAGE - 1));
        CP_COMMIT();

        const uint32_t st  = sbase + (kt & (NSTAGE - 1)) * STAGE_BYTES;
        const uint32_t sAh = st;
        const uint32_t sAl = st + TILE_BYTES;
        const uint32_t sB  = st + 2 * TILE_BYTES;

#pragma unroll
        for (int ks = 0; ks < 2; ks++) {
            const uint32_t ko = ks * 32;
            uint32_t a0[4][4], a1[4][4], b0[2][4];
#pragma unroll
            for (int i = 0; i < 4; i++) ldsm4(a0[i], sAh + aoff + ko + i * 16 * PAD * 2);
#pragma unroll
            for (int j2 = 0; j2 < 2; j2++) ldsm4(b0[j2], sB + boff + ko + j2 * 16 * PAD * 2);
#pragma unroll
            for (int i = 0; i < 4; i++)
#pragma unroll
                for (int j = 0; j < 4; j++)
                    mma16816(acc[i][j], a0[i], b0[j >> 1][(j & 1) * 2], b0[j >> 1][(j & 1) * 2 + 1]);
#pragma unroll
            for (int i = 0; i < 4; i++) ldsm4(a1[i], sAl + aoff + ko + i * 16 * PAD * 2);
#pragma unroll
            for (int i = 0; i < 4; i++)
#pragma unroll
                for (int j = 0; j < 4; j++)
                    mma16816(acc[i][j], a1[i], b0[j >> 1][(j & 1) * 2], b0[j >> 1][(j & 1) * 2 + 1]);
        }
        __syncthreads();
    }

    const int m_l = lane >> 2;
    const int n_l = (lane & 3) * 2;
#pragma unroll
    for (int j = 0; j < 4; j++) {
        const int n = bn + wn + j * 8 + n_l;
        const float2 b2 = *(const float2*)(bias + n);
#pragma unroll
        for (int i = 0; i < 4; i++) {
            const int m = bm + wm + i * 16 + m_l;
            float v[4];
            v[0] = acc[i][j][0] + b2.x;
            v[1] = acc[i][j][1] + b2.y;
            v[2] = acc[i][j][2] + b2.x;
            v[3] = acc[i][j][3] + b2.y;
            if (ACT == 1) {
#pragma unroll
                for (int r = 0; r < 4; r++)
                    v[r] = 0.5f * v[r] * (1.0f + erff(v[r] * 0.70710678118654752f));
            }
            if (OUT == 0) {
                float2 o0; o0.x = v[0]; o0.y = v[1];
                float2 o1; o1.x = v[2]; o1.y = v[3];
                *(float2*)(C + (size_t)m * N + n)       = o0;
                *(float2*)(C + (size_t)(m + 8) * N + n) = o1;
            } else {
                __half2 h0, l0, h1, l1;
                split2h(v[0], h0.x, l0.x); split2h(v[1], h0.y, l0.y);
                split2h(v[2], h1.x, l1.x); split2h(v[3], h1.y, l1.y);
                *(__half2*)(Ch + (size_t)m * N + n)       = h0;
                *(__half2*)(Cl + (size_t)m * N + n)       = l0;
                *(__half2*)(Ch + (size_t)(m + 8) * N + n) = h1;
                *(__half2*)(Cl + (size_t)(m + 8) * N + n) = l1;
            }
        }
    }
}

// ============================================================================
// Tensor-core flash attention.
// Block: 128 q-rows x (head, batch). 256 threads = 8 warps, 16 q-rows each.
// S = QK^T: 3-term (QhKh + QlKh + QhKl).  PV: 2-term (PhV + PlV), V = fp16 hi.
// K/V tiles (64 keys) double-buffered via cp.async from fp16 qkv buffers.
// ============================================================================
#define QP 72                              // padded halfs per smem row
#define QTILE_B (64 * QP * 2)              // 9216 bytes per 64x64 fp16 tile
#define AQ_BYTES (2 * 2 * QTILE_B)         // Qh+Ql, 128 rows = 36864
#define AST_BYTES (3 * QTILE_B)            // Kh, Kl, V per stage = 27648
#define ASMEM_TOTAL (AQ_BYTES + 2 * AST_BYTES)  // 92160

__global__ __launch_bounds__(256)
void attn_tc(const __half* __restrict__ qkvh, const __half* __restrict__ qkvl,
             __half* __restrict__ ctxh, __half* __restrict__ ctxl) {
    extern __shared__ char smem[];
    const uint32_t sb  = smem_u32(smem);
    const uint32_t sQh = sb;
    const uint32_t sQl = sb + 2 * QTILE_B;
    const uint32_t sSt = sb + AQ_BYTES;

    const int q0 = blockIdx.x * 128;
    const int h  = blockIdx.y;
    const int b  = blockIdx.z;
    const int tid  = threadIdx.x;
    const int wid  = tid >> 5;
    const int lane = tid & 31;
    const int g    = lane >> 3;
    const int rig  = lane & 7;

    const size_t rowbase = (size_t)b * S_ * (3 * E_) + h * (3 * HD_);

    // ---- load Q (hi/lo), 128 rows x 64 halfs each ----
    {
        const int r  = tid >> 1;           // 0..127
        const int cg = (tid & 1) * 4;      // chunk group
        const __half* sh = qkvh + rowbase + (size_t)(q0 + r) * (3 * E_) + cg * 8;
        const __half* sl = qkvl + rowbase + (size_t)(q0 + r) * (3 * E_) + cg * 8;
        const uint32_t d = r * QP * 2 + cg * 16;
#pragma unroll
        for (int j = 0; j < 4; j++) {
            cp16(sQh + d + j * 16, sh + j * 8);
            cp16(sQl + d + j * 16, sl + j * 8);
        }
    }
    CP_COMMIT();

    // ---- K/V stage loader: 64 rows, Kh/Kl/V ----
    auto load_kv = [&](int kt, int st) {
        const int r  = tid >> 2;           // 0..63
        const int cg = (tid & 3) * 2;      // 2 chunks of 16B
        const size_t grow = rowbase + (size_t)(kt * 64 + r) * (3 * E_);
        const uint32_t sd = sSt + st * AST_BYTES;
        const uint32_t d  = r * QP * 2 + cg * 16;
#pragma unroll
        for (int j = 0; j < 2; j++) {
            cp16(sd + 0 * QTILE_B + d + j * 16, qkvh + grow + HD_     + cg * 8 + j * 8);
            cp16(sd + 1 * QTILE_B + d + j * 16, qkvl + grow + HD_     + cg * 8 + j * 8);
            cp16(sd + 2 * QTILE_B + d + j * 16, qkvh + grow + 2 * HD_ + cg * 8 + j * 8);
        }
    };
    load_kv(0, 0); CP_COMMIT();

    // fragments & state
    uint32_t qh[4][4], ql[4][4];
    float oacc[8][4];
#pragma unroll
    for (int j = 0; j < 8; j++)
#pragma unroll
        for (int r = 0; r < 4; r++) oacc[j][r] = 0.f;
    float m0 = -1e30f, m1 = -1e30f, l0 = 0.f, l1 = 0.f;

    const uint32_t aoff = ((wid * 16 + (g & 1) * 8 + rig) * QP + (g >> 1) * 8) * 2;
    const uint32_t koff = (((g >> 1) * 8 + rig) * QP + (g & 1) * 8) * 2;
    const uint32_t voff = (((g & 1) * 8 + rig) * QP + (g >> 1) * 8) * 2;

    const int NT = S_ / 64;
    for (int kt = 0; kt < NT; kt++) {
        if (kt + 1 < NT) { load_kv(kt + 1, (kt + 1) & 1); CP_COMMIT(); CP_WAIT(1); }
        else             { CP_WAIT(0); }
        __syncthreads();

        if (kt == 0) {
#pragma unroll
            for (int t = 0; t < 4; t++) {
                ldsm4(qh[t], sQh + aoff + t * 32);
                ldsm4(ql[t], sQl + aoff + t * 32);
            }
        }

        const uint32_t st  = sSt + (kt & 1) * AST_BYTES;
        const uint32_t sKh = st;
        const uint32_t sKl = st + QTILE_B;
        const uint32_t sV  = st + 2 * QTILE_B;

        // ---- S = Q K^T (3-term) ----
        float sacc[8][4];
#pragma unroll
        for (int j = 0; j < 8; j++)
#pragma unroll
            for (int r = 0; r < 4; r++) sacc[j][r] = 0.f;

#pragma unroll
        for (int t = 0; t < 4; t++) {
#pragma unroll
            for (int np = 0; np < 4; np++) {
                uint32_t kh[4], kl[4];
                ldsm4(kh, sKh + koff + (np * 16 * QP + t * 16) * 2);
                ldsm4(kl, sKl + koff + (np * 16 * QP + t * 16) * 2);
#pragma unroll
                for (int jj = 0; jj < 2; jj++) {
                    const int j = np * 2 + jj;
                    mma16816(sacc[j], qh[t], kh[jj * 2], kh[jj * 2 + 1]);
                    mma16816(sacc[j], ql[t], kh[jj * 2], kh[jj * 2 + 1]);
                    mma16816(sacc[j], qh[t], kl[jj * 2], kl[jj * 2 + 1]);
                }
            }
        }

        // ---- online softmax ----
        const float SC = 0.125f;
        float mx0 = -1e30f, mx1 = -1e30f;
#pragma unroll
        for (int j = 0; j < 8; j++) {
#pragma unroll
            for (int r = 0; r < 4; r++) sacc[j][r] *= SC;
            mx0 = fmaxf(mx0, fmaxf(sacc[j][0], sacc[j][1]));
            mx1 = fmaxf(mx1, fmaxf(sacc[j][2], sacc[j][3]));
        }
        mx0 = fmaxf(mx0, __shfl_xor_sync(0xffffffffu, mx0, 1));
        mx0 = fmaxf(mx0, __shfl_xor_sync(0xffffffffu, mx0, 2));
        mx1 = fmaxf(mx1, __shfl_xor_sync(0xffffffffu, mx1, 1));
        mx1 = fmaxf(mx1, __shfl_xor_sync(0xffffffffu, mx1, 2));

        const float m0n = fmaxf(m0, mx0);
        const float m1n = fmaxf(m1, mx1);
        const float al0 = __expf(m0 - m0n);
        const float al1 = __expf(m1 - m1n);
        m0 = m0n; m1 = m1n;

        uint32_t aPh[4][4], aPl[4][4];
        float ps0 = 0.f, ps1 = 0.f;
#pragma unroll
        for (int j = 0; j < 8; j++) {
            const float p0 = __expf(sacc[j][0] - m0);
            const float p1 = __expf(sacc[j][1] - m0);
            const float p2 = __expf(sacc[j][2] - m1);
            const float p3 = __expf(sacc[j][3] - m1);
            ps0 += p0 + p1; ps1 += p2 + p3;
            __half h0, h1, h2, h3, e0, e1, e2, e3;
            split2h(p0, h0, e0); split2h(p1, h1, e1);
            split2h(p2, h2, e2); split2h(p3, h3, e3);
            const int t = j >> 1, s = (j & 1) * 2;
            aPh[t][s]     = packh2(h0, h1);
            aPh[t][s + 1] = packh2(h2, h3);
            aPl[t][s]     = packh2(e0, e1);
            aPl[t][s + 1] = packh2(e2, e3);
        }
        ps0 += __shfl_xor_sync(0xffffffffu, ps0, 1);
        ps0 += __shfl_xor_sync(0xffffffffu, ps0, 2);
        ps1 += __shfl_xor_sync(0xffffffffu, ps1, 1);
        ps1 += __shfl_xor_sync(0xffffffffu, ps1, 2);
        l0 = l0 * al0 + ps0;
        l1 = l1 * al1 + ps1;

#pragma unroll
        for (int j = 0; j < 8; j++) {
            oacc[j][0] *= al0; oacc[j][1] *= al0;
            oacc[j][2] *= al1; oacc[j][3] *= al1;
        }

        // ---- O += P V (2-term) ----
#pragma unroll
        for (int t = 0; t < 4; t++) {
#pragma unroll
            for (int dp = 0; dp < 4; dp++) {
                uint32_t vf[4];
                ldsm4t(vf, sV + voff + (t * 16 * QP + dp * 16) * 2);
#pragma unroll
                for (int jj = 0; jj < 2; jj++) {
                    const int jd = dp * 2 + jj;
                    mma16816(oacc[jd], aPh[t], vf[jj * 2], vf[jj * 2 + 1]);
                    mma16816(oacc[jd], aPl[t], vf[jj * 2], vf[jj * 2 + 1]);
                }
            }
        }
        __syncthreads();
    }

    // ---- epilogue: ctx = O / l, emit fp16 hi/lo ----
    const float li0 = 1.0f / l0;
    const float li1 = 1.0f / l1;
    const int r0 = q0 + wid * 16 + (lane >> 2);
    const int dcol = (lane & 3) * 2;
#pragma unroll
    for (int j = 0; j < 8; j++) {
        const size_t o0 = ((size_t)b * S_ + r0) * E_ + h * HD_ + j * 8 + dcol;
        const size_t o1 = o0 + 8 * E_;
        __half2 h0, l0h, h1, l1h;
        split2h(oacc[j][0] * li0, h0.x, l0h.x);
        split2h(oacc[j][1] * li0, h0.y, l0h.y);
        split2h(oacc[j][2] * li1, h1.x, l1h.x);
        split2h(oacc[j][3] * li1, h1.y, l1h.y);
        *(__half2*)(ctxh + o0) = h0;
        *(__half2*)(ctxl + o0) = l0h;
        *(__half2*)(ctxh + o1) = h1;
        *(__half2*)(ctxl + o1) = l1h;
    }
}

// ============================================================================
// Fused residual-add + LayerNorm; optional fp16 hi/lo emission
// ============================================================================
template<int EMIT>
__global__ __launch_bounds__(256)
void add_ln_kernel(const float* __restrict__ x, const float* __restrict__ y,
                   const float* __restrict__ g, const float* __restrict__ beta,
                   float* __restrict__ out,
                   __half* __restrict__ oh, __half* __restrict__ ol) {
    __shared__ float red1[8], red2[8];
    __shared__ float s_mean, s_rstd;
    const int row = blockIdx.x;
    const int tid = threadIdx.x;

    const float4 xv = ((const float4*)(x + (size_t)row * E_))[tid];
    const float4 yv = ((const float4*)(y + (size_t)row * E_))[tid];
    float v0 = xv.x + yv.x, v1 = xv.y + yv.y, v2 = xv.z + yv.z, v3 = xv.w + yv.w;

    float s  = v0 + v1 + v2 + v3;
    float ss = v0 * v0 + v1 * v1 + v2 * v2 + v3 * v3;
#pragma unroll
    for (int o = 16; o > 0; o >>= 1) {
        s  += __shfl_down_sync(0xffffffffu, s, o);
        ss += __shfl_down_sync(0xffffffffu, ss, o);
    }
    const int warp = tid >> 5, lane = tid & 31;
    if (lane == 0) { red1[warp] = s; red2[warp] = ss; }
    __syncthreads();
    if (tid == 0) {
        float ts = 0.f, tss = 0.f;
#pragma unroll
        for (int w = 0; w < 8; w++) { ts += red1[w]; tss += red2[w]; }
        float mean = ts * (1.0f / E_);
        float var  = tss * (1.0f / E_) - mean * mean;
        s_mean = mean;
        s_rstd = rsqrtf(var + 1e-5f);
    }
    __syncthreads();
    const float mean = s_mean, rstd = s_rstd;

    const float4 gv = ((const float4*)g)[tid];
    const float4 bv = ((const float4*)beta)[tid];
    float4 o;
    o.x = (v0 - mean) * rstd * gv.x + bv.x;
    o.y = (v1 - mean) * rstd * gv.y + bv.y;
    o.z = (v2 - mean) * rstd * gv.z + bv.z;
    o.w = (v3 - mean) * rstd * gv.w + bv.w;
    ((float4*)(out + (size_t)row * E_))[tid] = o;
    if (EMIT) {
        __half2 h01, h23, l01, l23;
        split2h(o.x, h01.x, l01.x); split2h(o.y, h01.y, l01.y);
        split2h(o.z, h23.x, l23.x); split2h(o.w, h23.y, l23.y);
        const size_t off = (size_t)row * E_ + tid * 4;
        *(__half2*)(oh + off)     = h01;
        *(__half2*)(oh + off + 2) = h23;
        *(__half2*)(ol + off)     = l01;
        *(__half2*)(ol + off + 2) = l23;
    }
}

// ============================================================================
// Launch
// ============================================================================
extern "C" void kernel_launch(void* const* d_in, const int* in_sizes, int n_in,
                              void* d_out, int out_size) {
    const float* x     = (const float*)d_in[0];
    const float* w_qkv = (const float*)d_in[1];
    const float* b_qkv = (const float*)d_in[2];
    const float* w_out = (const float*)d_in[3];
    const float* b_out = (const float*)d_in[4];
    const float* g1    = (const float*)d_in[5];
    const float* beta1 = (const float*)d_in[6];
    const float* g2    = (const float*)d_in[7];
    const float* beta2 = (const float*)d_in[8];
    const float* w1    = (const float*)d_in[9];
    const float* bf1   = (const float*)d_in[10];
    const float* w2    = (const float*)d_in[11];
    const float* bf2   = (const float*)d_in[12];
    float* out = (float*)d_out;

    float *tmp, *x1;
    cudaGetSymbolAddress((void**)&tmp,  g_tmp);
    cudaGetSymbolAddress((void**)&x1,   g_x1);

    __half *xh, *xl, *qkvh, *qkvl, *ctxh, *ctxl, *x1h, *x1l, *hh, *hl;
    __half *wqkvh, *wouth, *w1h, *w2h;
    cudaGetSymbolAddress((void**)&xh, g_xh);       cudaGetSymbolAddress((void**)&xl, g_xl);
    cudaGetSymbolAddress((void**)&qkvh, g_qkvh);   cudaGetSymbolAddress((void**)&qkvl, g_qkvl);
    cudaGetSymbolAddress((void**)&ctxh, g_ctxh);   cudaGetSymbolAddress((void**)&ctxl, g_ctxl);
    cudaGetSymbolAddress((void**)&x1h, g_x1h);     cudaGetSymbolAddress((void**)&x1l, g_x1l);
    cudaGetSymbolAddress((void**)&hh, g_hh);       cudaGetSymbolAddress((void**)&hl, g_hl);
    cudaGetSymbolAddress((void**)&wqkvh, g_wqkvh);
    cudaGetSymbolAddress((void**)&wouth, g_wouth);
    cudaGetSymbolAddress((void**)&w1h, g_w1h);
    cudaGetSymbolAddress((void**)&w2h, g_w2h);

    cudaFuncSetAttribute(attn_tc, cudaFuncAttributeMaxDynamicSharedMemorySize, ASMEM_TOTAL);
    cudaFuncSetAttribute(mma_gemm<0,0>, cudaFuncAttributeMaxDynamicSharedMemorySize, GSMEM_TOTAL);
    cudaFuncSetAttribute(mma_gemm<0,1>, cudaFuncAttributeMaxDynamicSharedMemorySize, GSMEM_TOTAL);
    cudaFuncSetAttribute(mma_gemm<1,1>, cudaFuncAttributeMaxDynamicSharedMemorySize, GSMEM_TOTAL);

    dim3 thr(256);

    // 0: weights -> fp16
    wconv_kernel<<<12288, thr>>>(w_qkv, w_out, w1, w2, wqkvh, wouth, w1h, w2h);

    // 1: x -> fp16 hi/lo
    split_kernel<<<(M_ * E_ / 4 + 255) / 256, 256>>>(x, xh, xl, M_ * E_ / 4);

    // 2: qkv = x @ w_qkv^T + b_qkv  -> fp16 hi/lo directly
    mma_gemm<0,1><<<dim3(3 * E_ / 128, M_ / 128), thr, GSMEM_TOTAL>>>(
        xh, xl, wqkvh, b_qkv, nullptr, qkvh, qkvl, M_, 3 * E_, E_);

    // 3: tensor-core flash attention -> ctx (fp16 hi/lo)
    attn_tc<<<dim3(S_ / 128, H_, B_), thr, ASMEM_TOTAL>>>(qkvh, qkvl, ctxh, ctxl);

    // 4: out-proj (fp32 out)
    mma_gemm<0,0><<<dim3(E_ / 128, M_ / 128), thr, GSMEM_TOTAL>>>(
        ctxh, ctxl, wouth, b_out, tmp, nullptr, nullptr, M_, E_, E_);

    // 5: residual + LN -> x1 (+ fp16 hi/lo)
    add_ln_kernel<1><<<M_, thr>>>(x, tmp, g1, beta1, x1, x1h, x1l);

    // 6: h = gelu(x1 @ w1^T + bf1) -> fp16 hi/lo directly
    mma_gemm<1,1><<<dim3(FF_ / 128, M_ / 128), thr, GSMEM_TOTAL>>>(
        x1h, x1l, w1h, bf1, nullptr, hh, hl, M_, FF_, E_);

    // 7: ffn2 (fp32 out)
    mma_gemm<0,0><<<dim3(E_ / 128, M_ / 128), thr, GSMEM_TOTAL>>>(
        hh, hl, w2h, bf2, tmp, nullptr, nullptr, M_, E_, FF_);

    // 8: residual + LN -> out
    add_ln_kernel<0><<<M_, thr>>>(x1, tmp, g2, beta2, out, nullptr, nullptr);
}

// round 7
// speedup vs baseline: 6.0795x; 1.1852x over previous
#include <cuda_runtime.h>
#include <cuda_fp16.h>
#include <math.h>
#include <stdint.h>

// ---------------- problem constants ----------------
#define B_  2
#define S_  2048
#define E_  1024
#define H_  16
#define HD_ 64
#define FF_ 4096
#define M_  (B_ * S_)          // 4096 rows

// ---------------- fp32 scratch ----------------
__device__ __align__(128) float g_tmp[(size_t)M_ * E_];
__device__ __align__(128) float g_x1 [(size_t)M_ * E_];

// ---------------- fp16 scratch ----------------
__device__ __align__(128) __half g_xh   [(size_t)M_ * E_],     g_xl   [(size_t)M_ * E_];
__device__ __align__(128) __half g_qkvh [(size_t)M_ * 3 * E_], g_qkvl [(size_t)M_ * 3 * E_];
__device__ __align__(128) __half g_ctxh [(size_t)M_ * E_],     g_ctxl [(size_t)M_ * E_];
__device__ __align__(128) __half g_x1h  [(size_t)M_ * E_],     g_x1l  [(size_t)M_ * E_];
__device__ __align__(128) __half g_hh   [(size_t)M_ * FF_],    g_hl   [(size_t)M_ * FF_];
__device__ __align__(128) __half g_wqkvh[(size_t)3 * E_ * E_];
__device__ __align__(128) __half g_wouth[(size_t)E_ * E_];
__device__ __align__(128) __half g_w1h  [(size_t)FF_ * E_];
__device__ __align__(128) __half g_w2h  [(size_t)E_ * FF_];

// ============================================================================
// helpers
// ============================================================================
__device__ __forceinline__ uint32_t smem_u32(const void* p) {
    uint32_t a;
    asm("{ .reg .u64 t; cvta.to.shared.u64 t, %1; cvt.u32.u64 %0, t; }"
        : "=r"(a) : "l"(p));
    return a;
}

__device__ __forceinline__ void cp16(uint32_t dst, const void* src) {
    asm volatile("cp.async.cg.shared.global [%0], [%1], 16;"
                 :: "r"(dst), "l"(src) : "memory");
}
#define CP_COMMIT()  asm volatile("cp.async.commit_group;" ::: "memory")
#define CP_WAIT(N)   asm volatile("cp.async.wait_group %0;" :: "n"(N) : "memory")

__device__ __forceinline__ void ldsm4(uint32_t* r, uint32_t addr) {
    asm volatile("ldmatrix.sync.aligned.m8n8.x4.shared.b16 {%0,%1,%2,%3}, [%4];"
                 : "=r"(r[0]), "=r"(r[1]), "=r"(r[2]), "=r"(r[3]) : "r"(addr));
}
__device__ __forceinline__ void ldsm4t(uint32_t* r, uint32_t addr) {
    asm volatile("ldmatrix.sync.aligned.m8n8.x4.trans.shared.b16 {%0,%1,%2,%3}, [%4];"
                 : "=r"(r[0]), "=r"(r[1]), "=r"(r[2]), "=r"(r[3]) : "r"(addr));
}

__device__ __forceinline__ void mma16816(float d[4], const uint32_t a[4],
                                         uint32_t b0, uint32_t b1) {
    asm volatile(
        "mma.sync.aligned.m16n8k16.row.col.f32.f16.f16.f32 "
        "{%0,%1,%2,%3}, {%4,%5,%6,%7}, {%8,%9}, {%0,%1,%2,%3};"
        : "+f"(d[0]), "+f"(d[1]), "+f"(d[2]), "+f"(d[3])
        : "r"(a[0]), "r"(a[1]), "r"(a[2]), "r"(a[3]), "r"(b0), "r"(b1));
}

__device__ __forceinline__ void split2h(float v, __half& h, __half& l) {
    h = __float2half_rn(v);
    l = __float2half_rn(v - __half2float(h));
}
__device__ __forceinline__ uint32_t packh2(__half a, __half b) {
    __half2 t; t.x = a; t.y = b;
    return *(uint32_t*)&t;
}

// ============================================================================
// Fused weight convert: fp32 -> fp16
// ============================================================================
__global__ __launch_bounds__(256)
void wconv_kernel(const float* __restrict__ s0, const float* __restrict__ s1,
                  const float* __restrict__ s2, const float* __restrict__ s3,
                  __half* __restrict__ d0, __half* __restrict__ d1,
                  __half* __restrict__ d2, __half* __restrict__ d3) {
    const int b = blockIdx.x;
    const float* s; __half* d; int base;
    if      (b < 3072) { s = s0; d = d0; base = b; }
    else if (b < 4096) { s = s1; d = d1; base = b - 3072; }
    else if (b < 8192) { s = s2; d = d2; base = b - 4096; }
    else               { s = s3; d = d3; base = b - 8192; }
    const int i = base * 256 + threadIdx.x;
    float4 v = ((const float4*)s)[i];
    ((__half2*)d)[2 * i]     = __floats2half2_rn(v.x, v.y);
    ((__half2*)d)[2 * i + 1] = __floats2half2_rn(v.z, v.w);
}

// ============================================================================
// Split fp32 -> (fp16 hi, fp16 lo)
// ============================================================================
__global__ __launch_bounds__(256)
void split_kernel(const float* __restrict__ src, __half* __restrict__ hi,
                  __half* __restrict__ lo, int n4) {
    int i = blockIdx.x * 256 + threadIdx.x;
    if (i >= n4) return;
    float4 v = ((const float4*)src)[i];
    __half2 h01, h23, l01, l23;
    split2h(v.x, h01.x, l01.x); split2h(v.y, h01.y, l01.y);
    split2h(v.z, h23.x, l23.x); split2h(v.w, h23.y, l23.y);
    ((__half2*)hi)[2 * i]     = h01;
    ((__half2*)hi)[2 * i + 1] = h23;
    ((__half2*)lo)[2 * i]     = l01;
    ((__half2*)lo)[2 * i + 1] = l23;
}

// ============================================================================
// mma.sync GEMM: C = (Ah+Al) @ B^T + bias, fp16 2-term split.
// CTA 128x128, K-tile 32, 8 warps (2Mx4N), 3-stage cp.async, 2 CTAs/SM.
// A-fragments transient (Ah then Al overwrite) to stay under 128 regs.
// ============================================================================
#define PAD   40
#define TILE_BYTES (128 * PAD * 2)         // 10240
#define STAGE_BYTES (3 * TILE_BYTES)       // Ah, Al, B = 30720
#define NSTAGE 3
#define GSMEM_TOTAL (NSTAGE * STAGE_BYTES) // 92160

template<int ACT, int OUT>
__global__ __launch_bounds__(256, 2)
void mma_gemm(const __half* __restrict__ Ah, const __half* __restrict__ Al,
              const __half* __restrict__ Bh,
              const float* __restrict__ bias,
              float* __restrict__ C,
              __half* __restrict__ Ch, __half* __restrict__ Cl,
              int M, int N, int K) {
    extern __shared__ char smem[];
    const uint32_t sbase = smem_u32(smem);
    const int tid  = threadIdx.x;
    const int bm   = blockIdx.y * 128;
    const int bn   = blockIdx.x * 128;

    const int wid  = tid >> 5;
    const int lane = tid & 31;
    const int wm   = (wid & 1) * 64;
    const int wn   = (wid >> 1) * 32;
    const int g    = lane >> 3;
    const int rig  = lane & 7;

    const __half* srcA_h = Ah + (size_t)bm * K;
    const __half* srcA_l = Al + (size_t)bm * K;
    const __half* srcB   = Bh + (size_t)bn * K;

    float acc[4][4][4];
#pragma unroll
    for (int i = 0; i < 4; i++)
#pragma unroll
        for (int j = 0; j < 4; j++)
#pragma unroll
            for (int r = 0; r < 4; r++) acc[i][j][r] = 0.f;

    const int nt = K >> 5;
    const int lrow = tid >> 2;
    const int lc4  = (tid & 3);

    auto load_stage = [&](int kt, int st) {
        const uint32_t sdst = sbase + st * STAGE_BYTES;
        const size_t koff = (size_t)kt * 32 + lc4 * 8;
        const uint32_t so = lc4 * 16;
#pragma unroll
        for (int half_ = 0; half_ < 2; half_++) {
            const int row = lrow + half_ * 64;
            const uint32_t rowo = row * PAD * 2 + so;
            const size_t gof = (size_t)row * K + koff;
            cp16(sdst + 0 * TILE_BYTES + rowo, srcA_h + gof);
            cp16(sdst + 1 * TILE_BYTES + rowo, srcA_l + gof);
            cp16(sdst + 2 * TILE_BYTES + rowo, srcB   + gof);
        }
    };

    load_stage(0, 0); CP_COMMIT();
    load_stage(1, 1); CP_COMMIT();

    const uint32_t aoff = ((wm + (g & 1) * 8 + rig) * PAD + (g >> 1) * 8) * 2;
    const uint32_t boff = ((wn + (g >> 1) * 8 + rig) * PAD + (g & 1) * 8) * 2;

    int stcur = 0;
    for (int kt = 0; kt < nt; kt++) {
        CP_WAIT(1);
        __syncthreads();
        if (kt + 2 < nt) {
            int stn = stcur + 2; if (stn >= NSTAGE) stn -= NSTAGE;
            load_stage(kt + 2, stn);
        }
        CP_COMMIT();

        const uint32_t st  = sbase + stcur * STAGE_BYTES;
        const uint32_t sAh = st;
        const uint32_t sAl = st + TILE_BYTES;
        const uint32_t sB  = st + 2 * TILE_BYTES;
        stcur++; if (stcur >= NSTAGE) stcur = 0;

#pragma unroll
        for (int ks = 0; ks < 2; ks++) {
            const uint32_t ko = ks * 32;
            uint32_t a0[4][4], b0[2][4];
#pragma unroll
            for (int j2 = 0; j2 < 2; j2++) ldsm4(b0[j2], sB + boff + ko + j2 * 16 * PAD * 2);
            // term 1: Ah
#pragma unroll
            for (int i = 0; i < 4; i++) ldsm4(a0[i], sAh + aoff + ko + i * 16 * PAD * 2);
#pragma unroll
            for (int i = 0; i < 4; i++)
#pragma unroll
                for (int j = 0; j < 4; j++)
                    mma16816(acc[i][j], a0[i], b0[j >> 1][(j & 1) * 2], b0[j >> 1][(j & 1) * 2 + 1]);
            // term 2: Al (overwrite a0)
#pragma unroll
            for (int i = 0; i < 4; i++) ldsm4(a0[i], sAl + aoff + ko + i * 16 * PAD * 2);
#pragma unroll
            for (int i = 0; i < 4; i++)
#pragma unroll
                for (int j = 0; j < 4; j++)
                    mma16816(acc[i][j], a0[i], b0[j >> 1][(j & 1) * 2], b0[j >> 1][(j & 1) * 2 + 1]);
        }
        __syncthreads();
    }

    const int m_l = lane >> 2;
    const int n_l = (lane & 3) * 2;
#pragma unroll
    for (int j = 0; j < 4; j++) {
        const int n = bn + wn + j * 8 + n_l;
        const float2 b2 = *(const float2*)(bias + n);
#pragma unroll
        for (int i = 0; i < 4; i++) {
            const int m = bm + wm + i * 16 + m_l;
            float v[4];
            v[0] = acc[i][j][0] + b2.x;
            v[1] = acc[i][j][1] + b2.y;
            v[2] = acc[i][j][2] + b2.x;
            v[3] = acc[i][j][3] + b2.y;
            if (ACT == 1) {
#pragma unroll
                for (int r = 0; r < 4; r++)
                    v[r] = 0.5f * v[r] * (1.0f + erff(v[r] * 0.70710678118654752f));
            }
            if (OUT == 0) {
                float2 o0; o0.x = v[0]; o0.y = v[1];
                float2 o1; o1.x = v[2]; o1.y = v[3];
                *(float2*)(C + (size_t)m * N + n)       = o0;
                *(float2*)(C + (size_t)(m + 8) * N + n) = o1;
            } else {
                __half2 h0, l0, h1, l1;
                split2h(v[0], h0.x, l0.x); split2h(v[1], h0.y, l0.y);
                split2h(v[2], h1.x, l1.x); split2h(v[3], h1.y, l1.y);
                *(__half2*)(Ch + (size_t)m * N + n)       = h0;
                *(__half2*)(Cl + (size_t)m * N + n)       = l0;
                *(__half2*)(Ch + (size_t)(m + 8) * N + n) = h1;
                *(__half2*)(Cl + (size_t)(m + 8) * N + n) = l1;
            }
        }
    }
}

// ============================================================================
// Tensor-core flash attention (Q frags transient; 2 CTAs/SM target).
// ============================================================================
#define QP 72
#define QTILE_B (64 * QP * 2)
#define AQ_BYTES (2 * 2 * QTILE_B)
#define AST_BYTES (3 * QTILE_B)
#define ASMEM_TOTAL (AQ_BYTES + 2 * AST_BYTES)  // 92160

__global__ __launch_bounds__(256, 2)
void attn_tc(const __half* __restrict__ qkvh, const __half* __restrict__ qkvl,
             __half* __restrict__ ctxh, __half* __restrict__ ctxl) {
    extern __shared__ char smem[];
    const uint32_t sb  = smem_u32(smem);
    const uint32_t sQh = sb;
    const uint32_t sQl = sb + 2 * QTILE_B;
    const uint32_t sSt = sb + AQ_BYTES;

    const int q0 = blockIdx.x * 128;
    const int h  = blockIdx.y;
    const int b  = blockIdx.z;
    const int tid  = threadIdx.x;
    const int wid  = tid >> 5;
    const int lane = tid & 31;
    const int g    = lane >> 3;
    const int rig  = lane & 7;

    const size_t rowbase = (size_t)b * S_ * (3 * E_) + h * (3 * HD_);

    // ---- load Q (hi/lo), 128 rows x 64 halfs ----
    {
        const int r  = tid >> 1;
        const int cg = (tid & 1) * 4;
        const __half* sh = qkvh + rowbase + (size_t)(q0 + r) * (3 * E_) + cg * 8;
        const __half* sl = qkvl + rowbase + (size_t)(q0 + r) * (3 * E_) + cg * 8;
        const uint32_t d = r * QP * 2 + cg * 16;
#pragma unroll
        for (int j = 0; j < 4; j++) {
            cp16(sQh + d + j * 16, sh + j * 8);
            cp16(sQl + d + j * 16, sl + j * 8);
        }
    }
    CP_COMMIT();

    auto load_kv = [&](int kt, int st) {
        const int r  = tid >> 2;
        const int cg = (tid & 3) * 2;
        const size_t grow = rowbase + (size_t)(kt * 64 + r) * (3 * E_);
        const uint32_t sd = sSt + st * AST_BYTES;
        const uint32_t d  = r * QP * 2 + cg * 16;
#pragma unroll
        for (int j = 0; j < 2; j++) {
            cp16(sd + 0 * QTILE_B + d + j * 16, qkvh + grow + HD_     + cg * 8 + j * 8);
            cp16(sd + 1 * QTILE_B + d + j * 16, qkvl + grow + HD_     + cg * 8 + j * 8);
            cp16(sd + 2 * QTILE_B + d + j * 16, qkvh + grow + 2 * HD_ + cg * 8 + j * 8);
        }
    };
    load_kv(0, 0); CP_COMMIT();

    float oacc[8][4];
#pragma unroll
    for (int j = 0; j < 8; j++)
#pragma unroll
        for (int r = 0; r < 4; r++) oacc[j][r] = 0.f;
    float m0 = -1e30f, m1 = -1e30f, l0 = 0.f, l1 = 0.f;

    const uint32_t aoff = ((wid * 16 + (g & 1) * 8 + rig) * QP + (g >> 1) * 8) * 2;
    const uint32_t koff = (((g >> 1) * 8 + rig) * QP + (g & 1) * 8) * 2;
    const uint32_t voff = (((g & 1) * 8 + rig) * QP + (g >> 1) * 8) * 2;

    const int NT = S_ / 64;
    for (int kt = 0; kt < NT; kt++) {
        if (kt + 1 < NT) { load_kv(kt + 1, (kt + 1) & 1); CP_COMMIT(); CP_WAIT(1); }
        else             { CP_WAIT(0); }
        __syncthreads();

        const uint32_t st  = sSt + (kt & 1) * AST_BYTES;
        const uint32_t sKh = st;
        const uint32_t sKl = st + QTILE_B;
        const uint32_t sV  = st + 2 * QTILE_B;

        // ---- S = Q K^T (3-term), Q frags transient ----
        float sacc[8][4];
#pragma unroll
        for (int j = 0; j < 8; j++)
#pragma unroll
            for (int r = 0; r < 4; r++) sacc[j][r] = 0.f;

#pragma unroll
        for (int t = 0; t < 4; t++) {
            uint32_t qhf[4], qlf[4];
            ldsm4(qhf, sQh + aoff + t * 32);
            ldsm4(qlf, sQl + aoff + t * 32);
#pragma unroll
            for (int np = 0; np < 4; np++) {
                uint32_t kh[4], kl[4];
                ldsm4(kh, sKh + koff + (np * 16 * QP + t * 16) * 2);
                ldsm4(kl, sKl + koff + (np * 16 * QP + t * 16) * 2);
#pragma unroll
                for (int jj = 0; jj < 2; jj++) {
                    const int j = np * 2 + jj;
                    mma16816(sacc[j], qhf, kh[jj * 2], kh[jj * 2 + 1]);
                    mma16816(sacc[j], qlf, kh[jj * 2], kh[jj * 2 + 1]);
                    mma16816(sacc[j], qhf, kl[jj * 2], kl[jj * 2 + 1]);
                }
            }
        }

        // ---- online softmax ----
        const float SC = 0.125f;
        float mx0 = -1e30f, mx1 = -1e30f;
#pragma unroll
        for (int j = 0; j < 8; j++) {
#pragma unroll
            for (int r = 0; r < 4; r++) sacc[j][r] *= SC;
            mx0 = fmaxf(mx0, fmaxf(sacc[j][0], sacc[j][1]));
            mx1 = fmaxf(mx1, fmaxf(sacc[j][2], sacc[j][3]));
        }
        mx0 = fmaxf(mx0, __shfl_xor_sync(0xffffffffu, mx0, 1));
        mx0 = fmaxf(mx0, __shfl_xor_sync(0xffffffffu, mx0, 2));
        mx1 = fmaxf(mx1, __shfl_xor_sync(0xffffffffu, mx1, 1));
        mx1 = fmaxf(mx1, __shfl_xor_sync(0xffffffffu, mx1, 2));

        const float m0n = fmaxf(m0, mx0);
        const float m1n = fmaxf(m1, mx1);
        const float al0 = __expf(m0 - m0n);
        const float al1 = __expf(m1 - m1n);
        m0 = m0n; m1 = m1n;

        uint32_t aPh[4][4], aPl[4][4];
        float ps0 = 0.f, ps1 = 0.f;
#pragma unroll
        for (int j = 0; j < 8; j++) {
            const float p0 = __expf(sacc[j][0] - m0);
            const float p1 = __expf(sacc[j][1] - m0);
            const float p2 = __expf(sacc[j][2] - m1);
            const float p3 = __expf(sacc[j][3] - m1);
            ps0 += p0 + p1; ps1 += p2 + p3;
            __half h0, h1, h2, h3, e0, e1, e2, e3;
            split2h(p0, h0, e0); split2h(p1, h1, e1);
            split2h(p2, h2, e2); split2h(p3, h3, e3);
            const int t = j >> 1, s = (j & 1) * 2;
            aPh[t][s]     = packh2(h0, h1);
            aPh[t][s + 1] = packh2(h2, h3);
            aPl[t][s]     = packh2(e0, e1);
            aPl[t][s + 1] = packh2(e2, e3);
        }
        ps0 += __shfl_xor_sync(0xffffffffu, ps0, 1);
        ps0 += __shfl_xor_sync(0xffffffffu, ps0, 2);
        ps1 += __shfl_xor_sync(0xffffffffu, ps1, 1);
        ps1 += __shfl_xor_sync(0xffffffffu, ps1, 2);
        l0 = l0 * al0 + ps0;
        l1 = l1 * al1 + ps1;

#pragma unroll
        for (int j = 0; j < 8; j++) {
            oacc[j][0] *= al0; oacc[j][1] *= al0;
            oacc[j][2] *= al1; oacc[j][3] *= al1;
        }

        // ---- O += P V (2-term) ----
#pragma unroll
        for (int t = 0; t < 4; t++) {
#pragma unroll
            for (int dp = 0; dp < 4; dp++) {
                uint32_t vf[4];
                ldsm4t(vf, sV + voff + (t * 16 * QP + dp * 16) * 2);
#pragma unroll
                for (int jj = 0; jj < 2; jj++) {
                    const int jd = dp * 2 + jj;
                    mma16816(oacc[jd], aPh[t], vf[jj * 2], vf[jj * 2 + 1]);
                    mma16816(oacc[jd], aPl[t], vf[jj * 2], vf[jj * 2 + 1]);
                }
            }
        }
        __syncthreads();
    }

    // ---- epilogue ----
    const float li0 = 1.0f / l0;
    const float li1 = 1.0f / l1;
    const int r0 = q0 + wid * 16 + (lane >> 2);
    const int dcol = (lane & 3) * 2;
#pragma unroll
    for (int j = 0; j < 8; j++) {
        const size_t o0 = ((size_t)b * S_ + r0) * E_ + h * HD_ + j * 8 + dcol;
        const size_t o1 = o0 + 8 * E_;
        __half2 h0, l0h, h1, l1h;
        split2h(oacc[j][0] * li0, h0.x, l0h.x);
        split2h(oacc[j][1] * li0, h0.y, l0h.y);
        split2h(oacc[j][2] * li1, h1.x, l1h.x);
        split2h(oacc[j][3] * li1, h1.y, l1h.y);
        *(__half2*)(ctxh + o0) = h0;
        *(__half2*)(ctxl + o0) = l0h;
        *(__half2*)(ctxh + o1) = h1;
        *(__half2*)(ctxl + o1) = l1h;
    }
}

// ============================================================================
// Fused residual-add + LayerNorm; optional fp16 hi/lo emission
// ============================================================================
template<int EMIT>
__global__ __launch_bounds__(256)
void add_ln_kernel(const float* __restrict__ x, const float* __restrict__ y,
                   const float* __restrict__ g, const float* __restrict__ beta,
                   float* __restrict__ out,
                   __half* __restrict__ oh, __half* __restrict__ ol) {
    __shared__ float red1[8], red2[8];
    __shared__ float s_mean, s_rstd;
    const int row = blockIdx.x;
    const int tid = threadIdx.x;

    const float4 xv = ((const float4*)(x + (size_t)row * E_))[tid];
    const float4 yv = ((const float4*)(y + (size_t)row * E_))[tid];
    float v0 = xv.x + yv.x, v1 = xv.y + yv.y, v2 = xv.z + yv.z, v3 = xv.w + yv.w;

    float s  = v0 + v1 + v2 + v3;
    float ss = v0 * v0 + v1 * v1 + v2 * v2 + v3 * v3;
#pragma unroll
    for (int o = 16; o > 0; o >>= 1) {
        s  += __shfl_down_sync(0xffffffffu, s, o);
        ss += __shfl_down_sync(0xffffffffu, ss, o);
    }
    const int warp = tid >> 5, lane = tid & 31;
    if (lane == 0) { red1[warp] = s; red2[warp] = ss; }
    __syncthreads();
    if (tid == 0) {
        float ts = 0.f, tss = 0.f;
#pragma unroll
        for (int w = 0; w < 8; w++) { ts += red1[w]; tss += red2[w]; }
        float mean = ts * (1.0f / E_);
        float var  = tss * (1.0f / E_) - mean * mean;
        s_mean = mean;
        s_rstd = rsqrtf(var + 1e-5f);
    }
    __syncthreads();
    const float mean = s_mean, rstd = s_rstd;

    const float4 gv = ((const float4*)g)[tid];
    const float4 bv = ((const float4*)beta)[tid];
    float4 o;
    o.x = (v0 - mean) * rstd * gv.x + bv.x;
    o.y = (v1 - mean) * rstd * gv.y + bv.y;
    o.z = (v2 - mean) * rstd * gv.z + bv.z;
    o.w = (v3 - mean) * rstd * gv.w + bv.w;
    ((float4*)(out + (size_t)row * E_))[tid] = o;
    if (EMIT) {
        __half2 h01, h23, l01, l23;
        split2h(o.x, h01.x, l01.x); split2h(o.y, h01.y, l01.y);
        split2h(o.z, h23.x, l23.x); split2h(o.w, h23.y, l23.y);
        const size_t off = (size_t)row * E_ + tid * 4;
        *(__half2*)(oh + off)     = h01;
        *(__half2*)(oh + off + 2) = h23;
        *(__half2*)(ol + off)     = l01;
        *(__half2*)(ol + off + 2) = l23;
    }
}

// ============================================================================
// Launch
// ============================================================================
extern "C" void kernel_launch(void* const* d_in, const int* in_sizes, int n_in,
                              void* d_out, int out_size) {
    const float* x     = (const float*)d_in[0];
    const float* w_qkv = (const float*)d_in[1];
    const float* b_qkv = (const float*)d_in[2];
    const float* w_out = (const float*)d_in[3];
    const float* b_out = (const float*)d_in[4];
    const float* g1    = (const float*)d_in[5];
    const float* beta1 = (const float*)d_in[6];
    const float* g2    = (const float*)d_in[7];
    const float* beta2 = (const float*)d_in[8];
    const float* w1    = (const float*)d_in[9];
    const float* bf1   = (const float*)d_in[10];
    const float* w2    = (const float*)d_in[11];
    const float* bf2   = (const float*)d_in[12];
    float* out = (float*)d_out;

    float *tmp, *x1;
    cudaGetSymbolAddress((void**)&tmp,  g_tmp);
    cudaGetSymbolAddress((void**)&x1,   g_x1);

    __half *xh, *xl, *qkvh, *qkvl, *ctxh, *ctxl, *x1h, *x1l, *hh, *hl;
    __half *wqkvh, *wouth, *w1h, *w2h;
    cudaGetSymbolAddress((void**)&xh, g_xh);       cudaGetSymbolAddress((void**)&xl, g_xl);
    cudaGetSymbolAddress((void**)&qkvh, g_qkvh);   cudaGetSymbolAddress((void**)&qkvl, g_qkvl);
    cudaGetSymbolAddress((void**)&ctxh, g_ctxh);   cudaGetSymbolAddress((void**)&ctxl, g_ctxl);
    cudaGetSymbolAddress((void**)&x1h, g_x1h);     cudaGetSymbolAddress((void**)&x1l, g_x1l);
    cudaGetSymbolAddress((void**)&hh, g_hh);       cudaGetSymbolAddress((void**)&hl, g_hl);
    cudaGetSymbolAddress((void**)&wqkvh, g_wqkvh);
    cudaGetSymbolAddress((void**)&wouth, g_wouth);
    cudaGetSymbolAddress((void**)&w1h, g_w1h);
    cudaGetSymbolAddress((void**)&w2h, g_w2h);

    cudaFuncSetAttribute(attn_tc, cudaFuncAttributeMaxDynamicSharedMemorySize, ASMEM_TOTAL);
    cudaFuncSetAttribute(mma_gemm<0,0>, cudaFuncAttributeMaxDynamicSharedMemorySize, GSMEM_TOTAL);
    cudaFuncSetAttribute(mma_gemm<0,1>, cudaFuncAttributeMaxDynamicSharedMemorySize, GSMEM_TOTAL);
    cudaFuncSetAttribute(mma_gemm<1,1>, cudaFuncAttributeMaxDynamicSharedMemorySize, GSMEM_TOTAL);

    dim3 thr(256);

    // 0: weights -> fp16
    wconv_kernel<<<12288, thr>>>(w_qkv, w_out, w1, w2, wqkvh, wouth, w1h, w2h);

    // 1: x -> fp16 hi/lo
    split_kernel<<<(M_ * E_ / 4 + 255) / 256, 256>>>(x, xh, xl, M_ * E_ / 4);

    // 2: qkv -> fp16 hi/lo directly
    mma_gemm<0,1><<<dim3(3 * E_ / 128, M_ / 128), thr, GSMEM_TOTAL>>>(
        xh, xl, wqkvh, b_qkv, nullptr, qkvh, qkvl, M_, 3 * E_, E_);

    // 3: tensor-core flash attention
    attn_tc<<<dim3(S_ / 128, H_, B_), thr, ASMEM_TOTAL>>>(qkvh, qkvl, ctxh, ctxl);

    // 4: out-proj (fp32 out)
    mma_gemm<0,0><<<dim3(E_ / 128, M_ / 128), thr, GSMEM_TOTAL>>>(
        ctxh, ctxl, wouth, b_out, tmp, nullptr, nullptr, M_, E_, E_);

    // 5: residual + LN -> x1 (+ fp16 hi/lo)
    add_ln_kernel<1><<<M_, thr>>>(x, tmp, g1, beta1, x1, x1h, x1l);

    // 6: h = gelu(x1 @ w1^T + bf1) -> fp16 hi/lo
    mma_gemm<1,1><<<dim3(FF_ / 128, M_ / 128), thr, GSMEM_TOTAL>>>(
        x1h, x1l, w1h, bf1, nullptr, hh, hl, M_, FF_, E_);

    // 7: ffn2 (fp32 out)
    mma_gemm<0,0><<<dim3(E_ / 128, M_ / 128), thr, GSMEM_TOTAL>>>(
        hh, hl, w2h, bf2, tmp, nullptr, nullptr, M_, E_, FF_);

    // 8: residual + LN -> out
    add_ln_kernel<0><<<M_, thr>>>(x1, tmp, g2, beta2, out, nullptr, nullptr);
}

// round 8
// speedup vs baseline: 6.4373x; 1.0589x over previous
#include <cuda_runtime.h>
#include <cuda_fp16.h>
#include <math.h>
#include <stdint.h>

// ---------------- problem constants ----------------
#define B_  2
#define S_  2048
#define E_  1024
#define H_  16
#define HD_ 64
#define FF_ 4096
#define M_  (B_ * S_)          // 4096 rows

// Q pre-scale: (1/sqrt(64)) * log2(e)  -> scores come out in log2 units
#define QSCALE_F 0.1803368801111244f

// ---------------- fp32 scratch ----------------
__device__ __align__(128) float g_tmp[(size_t)M_ * E_];
__device__ __align__(128) float g_x1 [(size_t)M_ * E_];

// ---------------- fp16 scratch ----------------
__device__ __align__(128) __half g_xh   [(size_t)M_ * E_],     g_xl   [(size_t)M_ * E_];
__device__ __align__(128) __half g_qkvh [(size_t)M_ * 3 * E_], g_qkvl [(size_t)M_ * 3 * E_];
__device__ __align__(128) __half g_ctxh [(size_t)M_ * E_],     g_ctxl [(size_t)M_ * E_];
__device__ __align__(128) __half g_x1h  [(size_t)M_ * E_],     g_x1l  [(size_t)M_ * E_];
__device__ __align__(128) __half g_hh   [(size_t)M_ * FF_],    g_hl   [(size_t)M_ * FF_];
__device__ __align__(128) __half g_wqkvh[(size_t)3 * E_ * E_];
__device__ __align__(128) __half g_wouth[(size_t)E_ * E_];
__device__ __align__(128) __half g_w1h  [(size_t)FF_ * E_];
__device__ __align__(128) __half g_w2h  [(size_t)E_ * FF_];

// ============================================================================
// helpers
// ============================================================================
__device__ __forceinline__ uint32_t smem_u32(const void* p) {
    uint32_t a;
    asm("{ .reg .u64 t; cvta.to.shared.u64 t, %1; cvt.u32.u64 %0, t; }"
        : "=r"(a) : "l"(p));
    return a;
}

__device__ __forceinline__ void cp16(uint32_t dst, const void* src) {
    asm volatile("cp.async.cg.shared.global [%0], [%1], 16;"
                 :: "r"(dst), "l"(src) : "memory");
}
#define CP_COMMIT()  asm volatile("cp.async.commit_group;" ::: "memory")
#define CP_WAIT(N)   asm volatile("cp.async.wait_group %0;" :: "n"(N) : "memory")

__device__ __forceinline__ void ldsm4(uint32_t* r, uint32_t addr) {
    asm volatile("ldmatrix.sync.aligned.m8n8.x4.shared.b16 {%0,%1,%2,%3}, [%4];"
                 : "=r"(r[0]), "=r"(r[1]), "=r"(r[2]), "=r"(r[3]) : "r"(addr));
}
__device__ __forceinline__ void ldsm4t(uint32_t* r, uint32_t addr) {
    asm volatile("ldmatrix.sync.aligned.m8n8.x4.trans.shared.b16 {%0,%1,%2,%3}, [%4];"
                 : "=r"(r[0]), "=r"(r[1]), "=r"(r[2]), "=r"(r[3]) : "r"(addr));
}

__device__ __forceinline__ void mma16816(float d[4], const uint32_t a[4],
                                         uint32_t b0, uint32_t b1) {
    asm volatile(
        "mma.sync.aligned.m16n8k16.row.col.f32.f16.f16.f32 "
        "{%0,%1,%2,%3}, {%4,%5,%6,%7}, {%8,%9}, {%0,%1,%2,%3};"
        : "+f"(d[0]), "+f"(d[1]), "+f"(d[2]), "+f"(d[3])
        : "r"(a[0]), "r"(a[1]), "r"(a[2]), "r"(a[3]), "r"(b0), "r"(b1));
}

__device__ __forceinline__ void split2h(float v, __half& h, __half& l) {
    h = __float2half_rn(v);
    l = __float2half_rn(v - __half2float(h));
}
__device__ __forceinline__ uint32_t packh2(__half a, __half b) {
    __half2 t; t.x = a; t.y = b;
    return *(uint32_t*)&t;
}

// ============================================================================
// Fused weight convert: fp32 -> fp16
// ============================================================================
__global__ __launch_bounds__(256)
void wconv_kernel(const float* __restrict__ s0, const float* __restrict__ s1,
                  const float* __restrict__ s2, const float* __restrict__ s3,
                  __half* __restrict__ d0, __half* __restrict__ d1,
                  __half* __restrict__ d2, __half* __restrict__ d3) {
    const int b = blockIdx.x;
    const float* s; __half* d; int base;
    if      (b < 3072) { s = s0; d = d0; base = b; }
    else if (b < 4096) { s = s1; d = d1; base = b - 3072; }
    else if (b < 8192) { s = s2; d = d2; base = b - 4096; }
    else               { s = s3; d = d3; base = b - 8192; }
    const int i = base * 256 + threadIdx.x;
    float4 v = ((const float4*)s)[i];
    ((__half2*)d)[2 * i]     = __floats2half2_rn(v.x, v.y);
    ((__half2*)d)[2 * i + 1] = __floats2half2_rn(v.z, v.w);
}

// ============================================================================
// Split fp32 -> (fp16 hi, fp16 lo)
// ============================================================================
__global__ __launch_bounds__(256)
void split_kernel(const float* __restrict__ src, __half* __restrict__ hi,
                  __half* __restrict__ lo, int n4) {
    int i = blockIdx.x * 256 + threadIdx.x;
    if (i >= n4) return;
    float4 v = ((const float4*)src)[i];
    __half2 h01, h23, l01, l23;
    split2h(v.x, h01.x, l01.x); split2h(v.y, h01.y, l01.y);
    split2h(v.z, h23.x, l23.x); split2h(v.w, h23.y, l23.y);
    ((__half2*)hi)[2 * i]     = h01;
    ((__half2*)hi)[2 * i + 1] = h23;
    ((__half2*)lo)[2 * i]     = l01;
    ((__half2*)lo)[2 * i + 1] = l23;
}

// ============================================================================
// mma.sync GEMM: C = (Ah+Al) @ B^T + bias, fp16 2-term split.
// CTA 128x128, K-tile 32, 8 warps (2Mx4N), 3-stage cp.async, 2 CTAs/SM.
// SCALEQ: multiply output by QSCALE for Q columns ((n % 192) < 64).
// ============================================================================
#define PAD   40
#define TILE_BYTES (128 * PAD * 2)
#define STAGE_BYTES (3 * TILE_BYTES)
#define NSTAGE 3
#define GSMEM_TOTAL (NSTAGE * STAGE_BYTES)

template<int ACT, int OUT, int SCALEQ>
__global__ __launch_bounds__(256, 2)
void mma_gemm(const __half* __restrict__ Ah, const __half* __restrict__ Al,
              const __half* __restrict__ Bh,
              const float* __restrict__ bias,
              float* __restrict__ C,
              __half* __restrict__ Ch, __half* __restrict__ Cl,
              int M, int N, int K) {
    extern __shared__ char smem[];
    const uint32_t sbase = smem_u32(smem);
    const int tid  = threadIdx.x;
    const int bm   = blockIdx.y * 128;
    const int bn   = blockIdx.x * 128;

    const int wid  = tid >> 5;
    const int lane = tid & 31;
    const int wm   = (wid & 1) * 64;
    const int wn   = (wid >> 1) * 32;
    const int g    = lane >> 3;
    const int rig  = lane & 7;

    const __half* srcA_h = Ah + (size_t)bm * K;
    const __half* srcA_l = Al + (size_t)bm * K;
    const __half* srcB   = Bh + (size_t)bn * K;

    float acc[4][4][4];
#pragma unroll
    for (int i = 0; i < 4; i++)
#pragma unroll
        for (int j = 0; j < 4; j++)
#pragma unroll
            for (int r = 0; r < 4; r++) acc[i][j][r] = 0.f;

    const int nt = K >> 5;
    const int lrow = tid >> 2;
    const int lc4  = (tid & 3);

    auto load_stage = [&](int kt, int st) {
        const uint32_t sdst = sbase + st * STAGE_BYTES;
        const size_t koff = (size_t)kt * 32 + lc4 * 8;
        const uint32_t so = lc4 * 16;
#pragma unroll
        for (int half_ = 0; half_ < 2; half_++) {
            const int row = lrow + half_ * 64;
            const uint32_t rowo = row * PAD * 2 + so;
            const size_t gof = (size_t)row * K + koff;
            cp16(sdst + 0 * TILE_BYTES + rowo, srcA_h + gof);
            cp16(sdst + 1 * TILE_BYTES + rowo, srcA_l + gof);
            cp16(sdst + 2 * TILE_BYTES + rowo, srcB   + gof);
        }
    };

    load_stage(0, 0); CP_COMMIT();
    load_stage(1, 1); CP_COMMIT();

    const uint32_t aoff = ((wm + (g & 1) * 8 + rig) * PAD + (g >> 1) * 8) * 2;
    const uint32_t boff = ((wn + (g >> 1) * 8 + rig) * PAD + (g & 1) * 8) * 2;

    int stcur = 0;
    for (int kt = 0; kt < nt; kt++) {
        CP_WAIT(1);
        __syncthreads();
        if (kt + 2 < nt) {
            int stn = stcur + 2; if (stn >= NSTAGE) stn -= NSTAGE;
            load_stage(kt + 2, stn);
        }
        CP_COMMIT();

        const uint32_t st  = sbase + stcur * STAGE_BYTES;
        const uint32_t sAh = st;
        const uint32_t sAl = st + TILE_BYTES;
        const uint32_t sB  = st + 2 * TILE_BYTES;
        stcur++; if (stcur >= NSTAGE) stcur = 0;

#pragma unroll
        for (int ks = 0; ks < 2; ks++) {
            const uint32_t ko = ks * 32;
            uint32_t a0[4][4], b0[2][4];
#pragma unroll
            for (int j2 = 0; j2 < 2; j2++) ldsm4(b0[j2], sB + boff + ko + j2 * 16 * PAD * 2);
#pragma unroll
            for (int i = 0; i < 4; i++) ldsm4(a0[i], sAh + aoff + ko + i * 16 * PAD * 2);
#pragma unroll
            for (int i = 0; i < 4; i++)
#pragma unroll
                for (int j = 0; j < 4; j++)
                    mma16816(acc[i][j], a0[i], b0[j >> 1][(j & 1) * 2], b0[j >> 1][(j & 1) * 2 + 1]);
#pragma unroll
            for (int i = 0; i < 4; i++) ldsm4(a0[i], sAl + aoff + ko + i * 16 * PAD * 2);
#pragma unroll
            for (int i = 0; i < 4; i++)
#pragma unroll
                for (int j = 0; j < 4; j++)
                    mma16816(acc[i][j], a0[i], b0[j >> 1][(j & 1) * 2], b0[j >> 1][(j & 1) * 2 + 1]);
        }
        // NOTE: no trailing __syncthreads — top sync of next iter orders
        // compute(kt) before any write to stage (kt+3)%3 == kt%3.
        __syncthreads();  // kept minimal: actually required only to order
                          // LDS reads of stage kt vs cp.async writes issued
                          // by faster warps at iter kt+1 top?  No — top sync
                          // covers it.  (Removed below.)
    }

    const int m_l = lane >> 2;
    const int n_l = (lane & 3) * 2;
#pragma unroll
    for (int j = 0; j < 4; j++) {
        const int n = bn + wn + j * 8 + n_l;
        const float2 b2 = *(const float2*)(bias + n);
        float qs = 1.f;
        if (SCALEQ) qs = ((n % 192) < 64) ? QSCALE_F : 1.f;
#pragma unroll
        for (int i = 0; i < 4; i++) {
            const int m = bm + wm + i * 16 + m_l;
            float v[4];
            v[0] = acc[i][j][0] + b2.x;
            v[1] = acc[i][j][1] + b2.y;
            v[2] = acc[i][j][2] + b2.x;
            v[3] = acc[i][j][3] + b2.y;
            if (ACT == 1) {
#pragma unroll
                for (int r = 0; r < 4; r++)
                    v[r] = 0.5f * v[r] * (1.0f + erff(v[r] * 0.70710678118654752f));
            }
            if (SCALEQ) {
#pragma unroll
                for (int r = 0; r < 4; r++) v[r] *= qs;
            }
            if (OUT == 0) {
                float2 o0; o0.x = v[0]; o0.y = v[1];
                float2 o1; o1.x = v[2]; o1.y = v[3];
                *(float2*)(C + (size_t)m * N + n)       = o0;
                *(float2*)(C + (size_t)(m + 8) * N + n) = o1;
            } else {
                __half2 h0, l0, h1, l1;
                split2h(v[0], h0.x, l0.x); split2h(v[1], h0.y, l0.y);
                split2h(v[2], h1.x, l1.x); split2h(v[3], h1.y, l1.y);
                *(__half2*)(Ch + (size_t)m * N + n)       = h0;
                *(__half2*)(Cl + (size_t)m * N + n)       = l0;
                *(__half2*)(Ch + (size_t)(m + 8) * N + n) = h1;
                *(__half2*)(Cl + (size_t)(m + 8) * N + n) = l1;
            }
        }
    }
}

// ============================================================================
// Tensor-core flash attention.
// Q pre-scaled by 0.125*log2(e) in the QKV GEMM -> scores in log2 units,
// softmax uses exp2f, no scaling in-kernel.
// S = Qh*Kh + Ql*Kh (2-term).  PV = Ph*V + Pl*V.  K/V stage: Kh + V only.
// One __syncthreads per k-tile.
// ============================================================================
#define QP 72
#define QTILE_B (64 * QP * 2)              // 9216
#define AQ_BYTES (2 * 2 * QTILE_B)         // Qh+Ql (128 rows) = 36864
#define AST_BYTES (2 * QTILE_B)            // Kh, V = 18432
#define ASMEM_TOTAL (AQ_BYTES + 2 * AST_BYTES)  // 73728

__global__ __launch_bounds__(256, 2)
void attn_tc(const __half* __restrict__ qkvh, const __half* __restrict__ qkvl,
             __half* __restrict__ ctxh, __half* __restrict__ ctxl) {
    extern __shared__ char smem[];
    const uint32_t sb  = smem_u32(smem);
    const uint32_t sQh = sb;
    const uint32_t sQl = sb + 2 * QTILE_B;
    const uint32_t sSt = sb + AQ_BYTES;

    const int q0 = blockIdx.x * 128;
    const int h  = blockIdx.y;
    const int b  = blockIdx.z;
    const int tid  = threadIdx.x;
    const int wid  = tid >> 5;
    const int lane = tid & 31;
    const int g    = lane >> 3;
    const int rig  = lane & 7;

    const size_t rowbase = (size_t)b * S_ * (3 * E_) + h * (3 * HD_);

    // ---- load Q (hi/lo), 128 rows x 64 halfs ----
    {
        const int r  = tid >> 1;
        const int cg = (tid & 1) * 4;
        const __half* sh = qkvh + rowbase + (size_t)(q0 + r) * (3 * E_) + cg * 8;
        const __half* sl = qkvl + rowbase + (size_t)(q0 + r) * (3 * E_) + cg * 8;
        const uint32_t d = r * QP * 2 + cg * 16;
#pragma unroll
        for (int j = 0; j < 4; j++) {
            cp16(sQh + d + j * 16, sh + j * 8);
            cp16(sQl + d + j * 16, sl + j * 8);
        }
    }

    auto load_kv = [&](int kt, int st) {
        const int r  = tid >> 2;
        const int cg = (tid & 3) * 2;
        const size_t grow = rowbase + (size_t)(kt * 64 + r) * (3 * E_);
        const uint32_t sd = sSt + st * AST_BYTES;
        const uint32_t d  = r * QP * 2 + cg * 16;
#pragma unroll
        for (int j = 0; j < 2; j++) {
            cp16(sd + 0 * QTILE_B + d + j * 16, qkvh + grow + HD_     + cg * 8 + j * 8);
            cp16(sd + 1 * QTILE_B + d + j * 16, qkvh + grow + 2 * HD_ + cg * 8 + j * 8);
        }
    };
    load_kv(0, 0);
    CP_COMMIT();

    float oacc[8][4];
#pragma unroll
    for (int j = 0; j < 8; j++)
#pragma unroll
        for (int r = 0; r < 4; r++) oacc[j][r] = 0.f;
    float m0 = -1e30f, m1 = -1e30f, l0 = 0.f, l1 = 0.f;

    const uint32_t aoff = ((wid * 16 + (g & 1) * 8 + rig) * QP + (g >> 1) * 8) * 2;
    const uint32_t koff = (((g >> 1) * 8 + rig) * QP + (g & 1) * 8) * 2;
    const uint32_t voff = (((g & 1) * 8 + rig) * QP + (g >> 1) * 8) * 2;

    const int NT = S_ / 64;
    for (int kt = 0; kt < NT; kt++) {
        CP_WAIT(0);
        __syncthreads();
        if (kt + 1 < NT) { load_kv(kt + 1, (kt + 1) & 1); CP_COMMIT(); }

        const uint32_t st  = sSt + (kt & 1) * AST_BYTES;
        const uint32_t sKh = st;
        const uint32_t sV  = st + QTILE_B;

        // ---- S = Q K^T (2-term) ----
        float sacc[8][4];
#pragma unroll
        for (int j = 0; j < 8; j++)
#pragma unroll
            for (int r = 0; r < 4; r++) sacc[j][r] = 0.f;

#pragma unroll
        for (int t = 0; t < 4; t++) {
            uint32_t qhf[4], qlf[4];
            ldsm4(qhf, sQh + aoff + t * 32);
            ldsm4(qlf, sQl + aoff + t * 32);
#pragma unroll
            for (int np = 0; np < 4; np++) {
                uint32_t kh[4];
                ldsm4(kh, sKh + koff + (np * 16 * QP + t * 16) * 2);
#pragma unroll
                for (int jj = 0; jj < 2; jj++) {
                    const int j = np * 2 + jj;
                    mma16816(sacc[j], qhf, kh[jj * 2], kh[jj * 2 + 1]);
                    mma16816(sacc[j], qlf, kh[jj * 2], kh[jj * 2 + 1]);
                }
            }
        }

        // ---- online softmax (log2 domain) ----
        float mx0 = -1e30f, mx1 = -1e30f;
#pragma unroll
        for (int j = 0; j < 8; j++) {
            mx0 = fmaxf(mx0, fmaxf(sacc[j][0], sacc[j][1]));
            mx1 = fmaxf(mx1, fmaxf(sacc[j][2], sacc[j][3]));
        }
        mx0 = fmaxf(mx0, __shfl_xor_sync(0xffffffffu, mx0, 1));
        mx0 = fmaxf(mx0, __shfl_xor_sync(0xffffffffu, mx0, 2));
        mx1 = fmaxf(mx1, __shfl_xor_sync(0xffffffffu, mx1, 1));
        mx1 = fmaxf(mx1, __shfl_xor_sync(0xffffffffu, mx1, 2));

        const float m0n = fmaxf(m0, mx0);
        const float m1n = fmaxf(m1, mx1);
        const float al0 = exp2f(m0 - m0n);
        const float al1 = exp2f(m1 - m1n);
        m0 = m0n; m1 = m1n;

        uint32_t aPh[4][4], aPl[4][4];
        float ps0 = 0.f, ps1 = 0.f;
#pragma unroll
        for (int j = 0; j < 8; j++) {
            const float p0 = exp2f(sacc[j][0] - m0);
            const float p1 = exp2f(sacc[j][1] - m0);
            const float p2 = exp2f(sacc[j][2] - m1);
            const float p3 = exp2f(sacc[j][3] - m1);
            ps0 += p0 + p1; ps1 += p2 + p3;
            __half h0, h1, h2, h3, e0, e1, e2, e3;
            split2h(p0, h0, e0); split2h(p1, h1, e1);
            split2h(p2, h2, e2); split2h(p3, h3, e3);
            const int t = j >> 1, s = (j & 1) * 2;
            aPh[t][s]     = packh2(h0, h1);
            aPh[t][s + 1] = packh2(h2, h3);
            aPl[t][s]     = packh2(e0, e1);
            aPl[t][s + 1] = packh2(e2, e3);
        }
        ps0 += __shfl_xor_sync(0xffffffffu, ps0, 1);
        ps0 += __shfl_xor_sync(0xffffffffu, ps0, 2);
        ps1 += __shfl_xor_sync(0xffffffffu, ps1, 1);
        ps1 += __shfl_xor_sync(0xffffffffu, ps1, 2);
        l0 = l0 * al0 + ps0;
        l1 = l1 * al1 + ps1;

#pragma unroll
        for (int j = 0; j < 8; j++) {
            oacc[j][0] *= al0; oacc[j][1] *= al0;
            oacc[j][2] *= al1; oacc[j][3] *= al1;
        }

        // ---- O += P V (2-term) ----
#pragma unroll
        for (int t = 0; t < 4; t++) {
#pragma unroll
            for (int dp = 0; dp < 4; dp++) {
                uint32_t vf[4];
                ldsm4t(vf, sV + voff + (t * 16 * QP + dp * 16) * 2);
#pragma unroll
                for (int jj = 0; jj < 2; jj++) {
                    const int jd = dp * 2 + jj;
                    mma16816(oacc[jd], aPh[t], vf[jj * 2], vf[jj * 2 + 1]);
                    mma16816(oacc[jd], aPl[t], vf[jj * 2], vf[jj * 2 + 1]);
                }
            }
        }
        __syncthreads();
    }

    // ---- epilogue ----
    const float li0 = 1.0f / l0;
    const float li1 = 1.0f / l1;
    const int r0 = q0 + wid * 16 + (lane >> 2);
    const int dcol = (lane & 3) * 2;
#pragma unroll
    for (int j = 0; j < 8; j++) {
        const size_t o0 = ((size_t)b * S_ + r0) * E_ + h * HD_ + j * 8 + dcol;
        const size_t o1 = o0 + 8 * E_;
        __half2 h0, l0h, h1, l1h;
        split2h(oacc[j][0] * li0, h0.x, l0h.x);
        split2h(oacc[j][1] * li0, h0.y, l0h.y);
        split2h(oacc[j][2] * li1, h1.x, l1h.x);
        split2h(oacc[j][3] * li1, h1.y, l1h.y);
        *(__half2*)(ctxh + o0) = h0;
        *(__half2*)(ctxl + o0) = l0h;
        *(__half2*)(ctxh + o1) = h1;
        *(__half2*)(ctxl + o1) = l1h;
    }
}

// ============================================================================
// Fused residual-add + LayerNorm; optional fp16 hi/lo emission
// ============================================================================
template<int EMIT>
__global__ __launch_bounds__(256)
void add_ln_kernel(const float* __restrict__ x, const float* __restrict__ y,
                   const float* __restrict__ g, const float* __restrict__ beta,
                   float* __restrict__ out,
                   __half* __restrict__ oh, __half* __restrict__ ol) {
    __shared__ float red1[8], red2[8];
    __shared__ float s_mean, s_rstd;
    const int row = blockIdx.x;
    const int tid = threadIdx.x;

    const float4 xv = ((const float4*)(x + (size_t)row * E_))[tid];
    const float4 yv = ((const float4*)(y + (size_t)row * E_))[tid];
    float v0 = xv.x + yv.x, v1 = xv.y + yv.y, v2 = xv.z + yv.z, v3 = xv.w + yv.w;

    float s  = v0 + v1 + v2 + v3;
    float ss = v0 * v0 + v1 * v1 + v2 * v2 + v3 * v3;
#pragma unroll
    for (int o = 16; o > 0; o >>= 1) {
        s  += __shfl_down_sync(0xffffffffu, s, o);
        ss += __shfl_down_sync(0xffffffffu, ss, o);
    }
    const int warp = tid >> 5, lane = tid & 31;
    if (lane == 0) { red1[warp] = s; red2[warp] = ss; }
    __syncthreads();
    if (tid == 0) {
        float ts = 0.f, tss = 0.f;
#pragma unroll
        for (int w = 0; w < 8; w++) { ts += red1[w]; tss += red2[w]; }
        float mean = ts * (1.0f / E_);
        float var  = tss * (1.0f / E_) - mean * mean;
        s_mean = mean;
        s_rstd = rsqrtf(var + 1e-5f);
    }
    __syncthreads();
    const float mean = s_mean, rstd = s_rstd;

    const float4 gv = ((const float4*)g)[tid];
    const float4 bv = ((const float4*)beta)[tid];
    float4 o;
    o.x = (v0 - mean) * rstd * gv.x + bv.x;
    o.y = (v1 - mean) * rstd * gv.y + bv.y;
    o.z = (v2 - mean) * rstd * gv.z + bv.z;
    o.w = (v3 - mean) * rstd * gv.w + bv.w;
    ((float4*)(out + (size_t)row * E_))[tid] = o;
    if (EMIT) {
        __half2 h01, h23, l01, l23;
        split2h(o.x, h01.x, l01.x); split2h(o.y, h01.y, l01.y);
        split2h(o.z, h23.x, l23.x); split2h(o.w, h23.y, l23.y);
        const size_t off = (size_t)row * E_ + tid * 4;
        *(__half2*)(oh + off)     = h01;
        *(__half2*)(oh + off + 2) = h23;
        *(__half2*)(ol + off)     = l01;
        *(__half2*)(ol + off + 2) = l23;
    }
}

// ============================================================================
// Launch
// ============================================================================
extern "C" void kernel_launch(void* const* d_in, const int* in_sizes, int n_in,
                              void* d_out, int out_size) {
    const float* x     = (const float*)d_in[0];
    const float* w_qkv = (const float*)d_in[1];
    const float* b_qkv = (const float*)d_in[2];
    const float* w_out = (const float*)d_in[3];
    const float* b_out = (const float*)d_in[4];
    const float* g1    = (const float*)d_in[5];
    const float* beta1 = (const float*)d_in[6];
    const float* g2    = (const float*)d_in[7];
    const float* beta2 = (const float*)d_in[8];
    const float* w1    = (const float*)d_in[9];
    const float* bf1   = (const float*)d_in[10];
    const float* w2    = (const float*)d_in[11];
    const float* bf2   = (const float*)d_in[12];
    float* out = (float*)d_out;

    float *tmp, *x1;
    cudaGetSymbolAddress((void**)&tmp,  g_tmp);
    cudaGetSymbolAddress((void**)&x1,   g_x1);

    __half *xh, *xl, *qkvh, *qkvl, *ctxh, *ctxl, *x1h, *x1l, *hh, *hl;
    __half *wqkvh, *wouth, *w1h, *w2h;
    cudaGetSymbolAddress((void**)&xh, g_xh);       cudaGetSymbolAddress((void**)&xl, g_xl);
    cudaGetSymbolAddress((void**)&qkvh, g_qkvh);   cudaGetSymbolAddress((void**)&qkvl, g_qkvl);
    cudaGetSymbolAddress((void**)&ctxh, g_ctxh);   cudaGetSymbolAddress((void**)&ctxl, g_ctxl);
    cudaGetSymbolAddress((void**)&x1h, g_x1h);     cudaGetSymbolAddress((void**)&x1l, g_x1l);
    cudaGetSymbolAddress((void**)&hh, g_hh);       cudaGetSymbolAddress((void**)&hl, g_hl);
    cudaGetSymbolAddress((void**)&wqkvh, g_wqkvh);
    cudaGetSymbolAddress((void**)&wouth, g_wouth);
    cudaGetSymbolAddress((void**)&w1h, g_w1h);
    cudaGetSymbolAddress((void**)&w2h, g_w2h);

    cudaFuncSetAttribute(attn_tc, cudaFuncAttributeMaxDynamicSharedMemorySize, ASMEM_TOTAL);
    cudaFuncSetAttribute(mma_gemm<0,0,0>, cudaFuncAttributeMaxDynamicSharedMemorySize, GSMEM_TOTAL);
    cudaFuncSetAttribute(mma_gemm<0,1,1>, cudaFuncAttributeMaxDynamicSharedMemorySize, GSMEM_TOTAL);
    cudaFuncSetAttribute(mma_gemm<1,1,0>, cudaFuncAttributeMaxDynamicSharedMemorySize, GSMEM_TOTAL);

    dim3 thr(256);

    // 0: weights -> fp16
    wconv_kernel<<<12288, thr>>>(w_qkv, w_out, w1, w2, wqkvh, wouth, w1h, w2h);

    // 1: x -> fp16 hi/lo
    split_kernel<<<(M_ * E_ / 4 + 255) / 256, 256>>>(x, xh, xl, M_ * E_ / 4);

    // 2: qkv -> fp16 hi/lo, Q columns pre-scaled by 0.125*log2(e)
    mma_gemm<0,1,1><<<dim3(3 * E_ / 128, M_ / 128), thr, GSMEM_TOTAL>>>(
        xh, xl, wqkvh, b_qkv, nullptr, qkvh, qkvl, M_, 3 * E_, E_);

    // 3: tensor-core flash attention
    attn_tc<<<dim3(S_ / 128, H_, B_), thr, ASMEM_TOTAL>>>(qkvh, qkvl, ctxh, ctxl);

    // 4: out-proj (fp32 out)
    mma_gemm<0,0,0><<<dim3(E_ / 128, M_ / 128), thr, GSMEM_TOTAL>>>(
        ctxh, ctxl, wouth, b_out, tmp, nullptr, nullptr, M_, E_, E_);

    // 5: residual + LN -> x1 (+ fp16 hi/lo)
    add_ln_kernel<1><<<M_, thr>>>(x, tmp, g1, beta1, x1, x1h, x1l);

    // 6: h = gelu(x1 @ w1^T + bf1) -> fp16 hi/lo
    mma_gemm<1,1,0><<<dim3(FF_ / 128, M_ / 128), thr, GSMEM_TOTAL>>>(
        x1h, x1l, w1h, bf1, nullptr, hh, hl, M_, FF_, E_);

    // 7: ffn2 (fp32 out)
    mma_gemm<0,0,0><<<dim3(E_ / 128, M_ / 128), thr, GSMEM_TOTAL>>>(
        hh, hl, w2h, bf2, tmp, nullptr, nullptr, M_, E_, FF_);

    // 8: residual + LN -> out
    add_ln_kernel<0><<<M_, thr>>>(x1, tmp, g2, beta2, out, nullptr, nullptr);
}

// round 10
// speedup vs baseline: 9.2083x; 1.4305x over previous
#include <cuda_runtime.h>
#include <cuda_fp16.h>
#include <math.h>
#include <stdint.h>

// ---------------- problem constants ----------------
#define B_  2
#define S_  2048
#define E_  1024
#define H_  16
#define HD_ 64
#define FF_ 4096
#define M_  (B_ * S_)          // 4096 rows

// Q pre-scale: (1/sqrt(64)) * log2(e)
#define QSCALE_F 0.1803368801111244f

// ---------------- fp32 scratch ----------------
__device__ __align__(128) float g_tmp[(size_t)M_ * E_];
__device__ __align__(128) float g_x1 [(size_t)M_ * E_];

// ---------------- fp16 scratch ----------------
__device__ __align__(128) __half g_xh   [(size_t)M_ * E_];
__device__ __align__(128) __half g_qkvh [(size_t)M_ * 3 * E_], g_qkvl [(size_t)M_ * 3 * E_];
__device__ __align__(128) __half g_ctxh [(size_t)M_ * E_];
__device__ __align__(128) __half g_x1h  [(size_t)M_ * E_];
__device__ __align__(128) __half g_hh   [(size_t)M_ * FF_];
__device__ __align__(128) __half g_wqkvh[(size_t)3 * E_ * E_];
__device__ __align__(128) __half g_wouth[(size_t)E_ * E_];
__device__ __align__(128) __half g_w1h  [(size_t)FF_ * E_];
__device__ __align__(128) __half g_w2h  [(size_t)E_ * FF_];

// ============================================================================
// helpers
// ============================================================================
__device__ __forceinline__ uint32_t smem_u32(const void* p) {
    uint32_t a;
    asm("{ .reg .u64 t; cvta.to.shared.u64 t, %1; cvt.u32.u64 %0, t; }"
        : "=r"(a) : "l"(p));
    return a;
}

__device__ __forceinline__ void cp16(uint32_t dst, const void* src) {
    asm volatile("cp.async.cg.shared.global [%0], [%1], 16;"
                 :: "r"(dst), "l"(src) : "memory");
}
#define CP_COMMIT()  asm volatile("cp.async.commit_group;" ::: "memory")
#define CP_WAIT(N)   asm volatile("cp.async.wait_group %0;" :: "n"(N) : "memory")

__device__ __forceinline__ void ldsm4(uint32_t* r, uint32_t addr) {
    asm volatile("ldmatrix.sync.aligned.m8n8.x4.shared.b16 {%0,%1,%2,%3}, [%4];"
                 : "=r"(r[0]), "=r"(r[1]), "=r"(r[2]), "=r"(r[3]) : "r"(addr));
}
__device__ __forceinline__ void ldsm4t(uint32_t* r, uint32_t addr) {
    asm volatile("ldmatrix.sync.aligned.m8n8.x4.trans.shared.b16 {%0,%1,%2,%3}, [%4];"
                 : "=r"(r[0]), "=r"(r[1]), "=r"(r[2]), "=r"(r[3]) : "r"(addr));
}

__device__ __forceinline__ void mma16816(float d[4], const uint32_t a[4],
                                         uint32_t b0, uint32_t b1) {
    asm volatile(
        "mma.sync.aligned.m16n8k16.row.col.f32.f16.f16.f32 "
        "{%0,%1,%2,%3}, {%4,%5,%6,%7}, {%8,%9}, {%0,%1,%2,%3};"
        : "+f"(d[0]), "+f"(d[1]), "+f"(d[2]), "+f"(d[3])
        : "r"(a[0]), "r"(a[1]), "r"(a[2]), "r"(a[3]), "r"(b0), "r"(b1));
}

__device__ __forceinline__ void split2h(float v, __half& h, __half& l) {
    h = __float2half_rn(v);
    l = __float2half_rn(v - __half2float(h));
}
__device__ __forceinline__ uint32_t packh2(__half a, __half b) {
    __half2 t; t.x = a; t.y = b;
    return *(uint32_t*)&t;
}

// ============================================================================
// Fused fp32 -> fp16 convert: 4 weights + x in one launch.
// block ranges (256 thr, one float4 each):
//   wqkv [0,3072)  wout [3072,4096)  w1 [4096,8192)  w2 [8192,12288)
//   x    [12288,16384)   (x = 4096*1024 floats = 4096 blocks)
// ============================================================================
__global__ __launch_bounds__(256)
void conv_kernel(const float* __restrict__ s0, const float* __restrict__ s1,
                 const float* __restrict__ s2, const float* __restrict__ s3,
                 const float* __restrict__ s4,
                 __half* __restrict__ d0, __half* __restrict__ d1,
                 __half* __restrict__ d2, __half* __restrict__ d3,
                 __half* __restrict__ d4) {
    const int b = blockIdx.x;
    const float* s; __half* d; int base;
    if      (b < 3072)  { s = s0; d = d0; base = b; }
    else if (b < 4096)  { s = s1; d = d1; base = b - 3072; }
    else if (b < 8192)  { s = s2; d = d2; base = b - 4096; }
    else if (b < 12288) { s = s3; d = d3; base = b - 8192; }
    else                { s = s4; d = d4; base = b - 12288; }
    const int i = base * 256 + threadIdx.x;
    float4 v = ((const float4*)s)[i];
    ((__half2*)d)[2 * i]     = __floats2half2_rn(v.x, v.y);
    ((__half2*)d)[2 * i + 1] = __floats2half2_rn(v.z, v.w);
}

// ============================================================================
// mma.sync HGEMM: C = A[M,K] @ B[N,K]^T + bias (A,B fp16 single).
// CTA 128x128, K-tile 32, 8 warps (2Mx4N), 4-stage cp.async, 2 CTAs/SM.
// ACT: 0/1 GELU.  OUT: 0 fp32, 1 fp16 hi+lo, 2 fp16 hi only.
// SCALEQ: Q columns ((n%192)<64) scaled by QSCALE (for qkv GEMM).
// ============================================================================
#define PAD   40
#define TILE_BYTES (128 * PAD * 2)           // 10240
#define STAGE_BYTES (2 * TILE_BYTES)         // A, B = 20480
#define NSTAGE 4
#define GSMEM_TOTAL (NSTAGE * STAGE_BYTES)   // 81920

template<int ACT, int OUT, int SCALEQ>
__global__ __launch_bounds__(256, 2)
void mma_gemm(const __half* __restrict__ A,
              const __half* __restrict__ Bh,
              const float* __restrict__ bias,
              float* __restrict__ C,
              __half* __restrict__ Ch, __half* __restrict__ Cl,
              int M, int N, int K) {
    extern __shared__ char smem[];
    const uint32_t sbase = smem_u32(smem);
    const int tid  = threadIdx.x;
    const int bm   = blockIdx.y * 128;
    const int bn   = blockIdx.x * 128;

    const int wid  = tid >> 5;
    const int lane = tid & 31;
    const int wm   = (wid & 1) * 64;
    const int wn   = (wid >> 1) * 32;
    const int g    = lane >> 3;
    const int rig  = lane & 7;

    const __half* srcA = A  + (size_t)bm * K;
    const __half* srcB = Bh + (size_t)bn * K;

    float acc[4][4][4];
#pragma unroll
    for (int i = 0; i < 4; i++)
#pragma unroll
        for (int j = 0; j < 4; j++)
#pragma unroll
            for (int r = 0; r < 4; r++) acc[i][j][r] = 0.f;

    const int nt = K >> 5;
    const int lrow = tid >> 2;
    const int lc4  = (tid & 3);

    auto load_stage = [&](int kt, int st) {
        const uint32_t sdst = sbase + st * STAGE_BYTES;
        const size_t koff = (size_t)kt * 32 + lc4 * 8;
        const uint32_t so = lc4 * 16;
#pragma unroll
        for (int half_ = 0; half_ < 2; half_++) {
            const int row = lrow + half_ * 64;
            const uint32_t rowo = row * PAD * 2 + so;
            const size_t gof = (size_t)row * K + koff;
            cp16(sdst + 0 * TILE_BYTES + rowo, srcA + gof);
            cp16(sdst + 1 * TILE_BYTES + rowo, srcB + gof);
        }
    };

    load_stage(0, 0); CP_COMMIT();
    load_stage(1, 1); CP_COMMIT();
    load_stage(2, 2); CP_COMMIT();

    const uint32_t aoff = ((wm + (g & 1) * 8 + rig) * PAD + (g >> 1) * 8) * 2;
    const uint32_t boff = ((wn + (g >> 1) * 8 + rig) * PAD + (g & 1) * 8) * 2;

    int stcur = 0;
    for (int kt = 0; kt < nt; kt++) {
        CP_WAIT(2);
        __syncthreads();
        if (kt + 3 < nt) {
            int stn = stcur + 3; if (stn >= NSTAGE) stn -= NSTAGE;
            load_stage(kt + 3, stn);
        }
        CP_COMMIT();

        const uint32_t st = sbase + stcur * STAGE_BYTES;
        const uint32_t sA = st;
        const uint32_t sB = st + TILE_BYTES;
        stcur++; if (stcur >= NSTAGE) stcur = 0;

#pragma unroll
        for (int ks = 0; ks < 2; ks++) {
            const uint32_t ko = ks * 32;
            uint32_t a0[4][4], b0[2][4];
#pragma unroll
            for (int j2 = 0; j2 < 2; j2++) ldsm4(b0[j2], sB + boff + ko + j2 * 16 * PAD * 2);
#pragma unroll
            for (int i = 0; i < 4; i++) ldsm4(a0[i], sA + aoff + ko + i * 16 * PAD * 2);
#pragma unroll
            for (int i = 0; i < 4; i++)
#pragma unroll
                for (int j = 0; j < 4; j++)
                    mma16816(acc[i][j], a0[i], b0[j >> 1][(j & 1) * 2], b0[j >> 1][(j & 1) * 2 + 1]);
        }
        // no trailing sync: top sync of iter kt+1 orders compute(kt) reads
        // before loads into stage (kt+4)%4 == kt%4.
    }

    const int m_l = lane >> 2;
    const int n_l = (lane & 3) * 2;
#pragma unroll
    for (int j = 0; j < 4; j++) {
        const int n = bn + wn + j * 8 + n_l;
        const float2 b2 = *(const float2*)(bias + n);
        float qs = 1.f;
        if (SCALEQ) qs = ((n % 192) < 64) ? QSCALE_F : 1.f;
#pragma unroll
        for (int i = 0; i < 4; i++) {
            const int m = bm + wm + i * 16 + m_l;
            float v[4];
            v[0] = acc[i][j][0] + b2.x;
            v[1] = acc[i][j][1] + b2.y;
            v[2] = acc[i][j][2] + b2.x;
            v[3] = acc[i][j][3] + b2.y;
            if (ACT == 1) {
#pragma unroll
                for (int r = 0; r < 4; r++)
                    v[r] = 0.5f * v[r] * (1.0f + erff(v[r] * 0.70710678118654752f));
            }
            if (SCALEQ) {
#pragma unroll
                for (int r = 0; r < 4; r++) v[r] *= qs;
            }
            if (OUT == 0) {
                float2 o0; o0.x = v[0]; o0.y = v[1];
                float2 o1; o1.x = v[2]; o1.y = v[3];
                *(float2*)(C + (size_t)m * N + n)       = o0;
                *(float2*)(C + (size_t)(m + 8) * N + n) = o1;
            } else if (OUT == 1) {
                __half2 h0, l0, h1, l1;
                split2h(v[0], h0.x, l0.x); split2h(v[1], h0.y, l0.y);
                split2h(v[2], h1.x, l1.x); split2h(v[3], h1.y, l1.y);
                *(__half2*)(Ch + (size_t)m * N + n)       = h0;
                *(__half2*)(Cl + (size_t)m * N + n)       = l0;
                *(__half2*)(Ch + (size_t)(m + 8) * N + n) = h1;
                *(__half2*)(Cl + (size_t)(m + 8) * N + n) = l1;
            } else {
                *(__half2*)(Ch + (size_t)m * N + n)       = __floats2half2_rn(v[0], v[1]);
                *(__half2*)(Ch + (size_t)(m + 8) * N + n) = __floats2half2_rn(v[2], v[3]);
            }
        }
    }
}

// ============================================================================
// Tensor-core flash attention (2-term S via Q hi/lo; 2-term PV; exp2 domain).
// ============================================================================
#define QP 72
#define QTILE_B (64 * QP * 2)
#define AQ_BYTES (2 * 2 * QTILE_B)
#define AST_BYTES (2 * QTILE_B)
#define ASMEM_TOTAL (AQ_BYTES + 2 * AST_BYTES)  // 73728

__global__ __launch_bounds__(256, 2)
void attn_tc(const __half* __restrict__ qkvh, const __half* __restrict__ qkvl,
             __half* __restrict__ ctxh) {
    extern __shared__ char smem[];
    const uint32_t sb  = smem_u32(smem);
    const uint32_t sQh = sb;
    const uint32_t sQl = sb + 2 * QTILE_B;
    const uint32_t sSt = sb + AQ_BYTES;

    const int q0 = blockIdx.x * 128;
    const int h  = blockIdx.y;
    const int b  = blockIdx.z;
    const int tid  = threadIdx.x;
    const int wid  = tid >> 5;
    const int lane = tid & 31;
    const int g    = lane >> 3;
    const int rig  = lane & 7;

    const size_t rowbase = (size_t)b * S_ * (3 * E_) + h * (3 * HD_);

    // Q hi/lo
    {
        const int r  = tid >> 1;
        const int cg = (tid & 1) * 4;
        const __half* sh = qkvh + rowbase + (size_t)(q0 + r) * (3 * E_) + cg * 8;
        const __half* sl = qkvl + rowbase + (size_t)(q0 + r) * (3 * E_) + cg * 8;
        const uint32_t d = r * QP * 2 + cg * 16;
#pragma unroll
        for (int j = 0; j < 4; j++) {
            cp16(sQh + d + j * 16, sh + j * 8);
            cp16(sQl + d + j * 16, sl + j * 8);
        }
    }

    auto load_kv = [&](int kt, int st) {
        const int r  = tid >> 2;
        const int cg = (tid & 3) * 2;
        const size_t grow = rowbase + (size_t)(kt * 64 + r) * (3 * E_);
        const uint32_t sd = sSt + st * AST_BYTES;
        const uint32_t d  = r * QP * 2 + cg * 16;
#pragma unroll
        for (int j = 0; j < 2; j++) {
            cp16(sd + 0 * QTILE_B + d + j * 16, qkvh + grow + HD_     + cg * 8 + j * 8);
            cp16(sd + 1 * QTILE_B + d + j * 16, qkvh + grow + 2 * HD_ + cg * 8 + j * 8);
        }
    };
    load_kv(0, 0);
    CP_COMMIT();

    float oacc[8][4];
#pragma unroll
    for (int j = 0; j < 8; j++)
#pragma unroll
        for (int r = 0; r < 4; r++) oacc[j][r] = 0.f;
    float m0 = -1e30f, m1 = -1e30f, l0 = 0.f, l1 = 0.f;

    const uint32_t aoff = ((wid * 16 + (g & 1) * 8 + rig) * QP + (g >> 1) * 8) * 2;
    const uint32_t koff = (((g >> 1) * 8 + rig) * QP + (g & 1) * 8) * 2;
    const uint32_t voff = (((g & 1) * 8 + rig) * QP + (g >> 1) * 8) * 2;

    const int NT = S_ / 64;
    for (int kt = 0; kt < NT; kt++) {
        CP_WAIT(0);
        __syncthreads();
        if (kt + 1 < NT) { load_kv(kt + 1, (kt + 1) & 1); CP_COMMIT(); }

        const uint32_t st  = sSt + (kt & 1) * AST_BYTES;
        const uint32_t sKh = st;
        const uint32_t sV  = st + QTILE_B;

        // S = (Qh+Ql) Kh^T
        float sacc[8][4];
#pragma unroll
        for (int j = 0; j < 8; j++)
#pragma unroll
            for (int r = 0; r < 4; r++) sacc[j][r] = 0.f;

#pragma unroll
        for (int t = 0; t < 4; t++) {
            uint32_t qhf[4], qlf[4];
            ldsm4(qhf, sQh + aoff + t * 32);
            ldsm4(qlf, sQl + aoff + t * 32);
#pragma unroll
            for (int np = 0; np < 4; np++) {
                uint32_t kh[4];
                ldsm4(kh, sKh + koff + (np * 16 * QP + t * 16) * 2);
#pragma unroll
                for (int jj = 0; jj < 2; jj++) {
                    const int j = np * 2 + jj;
                    mma16816(sacc[j], qhf, kh[jj * 2], kh[jj * 2 + 1]);
                    mma16816(sacc[j], qlf, kh[jj * 2], kh[jj * 2 + 1]);
                }
            }
        }

        // online softmax (log2 domain)
        float mx0 = -1e30f, mx1 = -1e30f;
#pragma unroll
        for (int j = 0; j < 8; j++) {
            mx0 = fmaxf(mx0, fmaxf(sacc[j][0], sacc[j][1]));
            mx1 = fmaxf(mx1, fmaxf(sacc[j][2], sacc[j][3]));
        }
        mx0 = fmaxf(mx0, __shfl_xor_sync(0xffffffffu, mx0, 1));
        mx0 = fmaxf(mx0, __shfl_xor_sync(0xffffffffu, mx0, 2));
        mx1 = fmaxf(mx1, __shfl_xor_sync(0xffffffffu, mx1, 1));
        mx1 = fmaxf(mx1, __shfl_xor_sync(0xffffffffu, mx1, 2));

        const float m0n = fmaxf(m0, mx0);
        const float m1n = fmaxf(m1, mx1);
        const float al0 = exp2f(m0 - m0n);
        const float al1 = exp2f(m1 - m1n);
        m0 = m0n; m1 = m1n;

        uint32_t aPh[4][4], aPl[4][4];
        float ps0 = 0.f, ps1 = 0.f;
#pragma unroll
        for (int j = 0; j < 8; j++) {
            const float p0 = exp2f(sacc[j][0] - m0);
            const float p1 = exp2f(sacc[j][1] - m0);
            const float p2 = exp2f(sacc[j][2] - m1);
            const float p3 = exp2f(sacc[j][3] - m1);
            ps0 += p0 + p1; ps1 += p2 + p3;
            __half h0, h1, h2, h3, e0, e1, e2, e3;
            split2h(p0, h0, e0); split2h(p1, h1, e1);
            split2h(p2, h2, e2); split2h(p3, h3, e3);
            const int t = j >> 1, s = (j & 1) * 2;
            aPh[t][s]     = packh2(h0, h1);
            aPh[t][s + 1] = packh2(h2, h3);
            aPl[t][s]     = packh2(e0, e1);
            aPl[t][s + 1] = packh2(e2, e3);
        }
        ps0 += __shfl_xor_sync(0xffffffffu, ps0, 1);
        ps0 += __shfl_xor_sync(0xffffffffu, ps0, 2);
        ps1 += __shfl_xor_sync(0xffffffffu, ps1, 1);
        ps1 += __shfl_xor_sync(0xffffffffu, ps1, 2);
        l0 = l0 * al0 + ps0;
        l1 = l1 * al1 + ps1;

#pragma unroll
        for (int j = 0; j < 8; j++) {
            oacc[j][0] *= al0; oacc[j][1] *= al0;
            oacc[j][2] *= al1; oacc[j][3] *= al1;
        }

        // O += (Ph+Pl) V
#pragma unroll
        for (int t = 0; t < 4; t++) {
#pragma unroll
            for (int dp = 0; dp < 4; dp++) {
                uint32_t vf[4];
                ldsm4t(vf, sV + voff + (t * 16 * QP + dp * 16) * 2);
#pragma unroll
                for (int jj = 0; jj < 2; jj++) {
                    const int jd = dp * 2 + jj;
                    mma16816(oacc[jd], aPh[t], vf[jj * 2], vf[jj * 2 + 1]);
                    mma16816(oacc[jd], aPl[t], vf[jj * 2], vf[jj * 2 + 1]);
                }
            }
        }
    }

    // epilogue: ctx hi only
    const float li0 = 1.0f / l0;
    const float li1 = 1.0f / l1;
    const int r0 = q0 + wid * 16 + (lane >> 2);
    const int dcol = (lane & 3) * 2;
#pragma unroll
    for (int j = 0; j < 8; j++) {
        const size_t o0 = ((size_t)b * S_ + r0) * E_ + h * HD_ + j * 8 + dcol;
        const size_t o1 = o0 + 8 * E_;
        *(__half2*)(ctxh + o0) = __floats2half2_rn(oacc[j][0] * li0, oacc[j][1] * li0);
        *(__half2*)(ctxh + o1) = __floats2half2_rn(oacc[j][2] * li1, oacc[j][3] * li1);
    }
}

// ============================================================================
// Fused residual-add + LayerNorm; optional fp16 (hi only) emission
// ============================================================================
template<int EMIT>
__global__ __launch_bounds__(256)
void add_ln_kernel(const float* __restrict__ x, const float* __restrict__ y,
                   const float* __restrict__ g, const float* __restrict__ beta,
                   float* __restrict__ out, __half* __restrict__ oh) {
    __shared__ float red1[8], red2[8];
    __shared__ float s_mean, s_rstd;
    const int row = blockIdx.x;
    const int tid = threadIdx.x;

    const float4 xv = ((const float4*)(x + (size_t)row * E_))[tid];
    const float4 yv = ((const float4*)(y + (size_t)row * E_))[tid];
    float v0 = xv.x + yv.x, v1 = xv.y + yv.y, v2 = xv.z + yv.z, v3 = xv.w + yv.w;

    float s  = v0 + v1 + v2 + v3;
    float ss = v0 * v0 + v1 * v1 + v2 * v2 + v3 * v3;
#pragma unroll
    for (int o = 16; o > 0; o >>= 1) {
        s  += __shfl_down_sync(0xffffffffu, s, o);
        ss += __shfl_down_sync(0xffffffffu, ss, o);
    }
    const int warp = tid >> 5, lane = tid & 31;
    if (lane == 0) { red1[warp] = s; red2[warp] = ss; }
    __syncthreads();
    if (tid == 0) {
        float ts = 0.f, tss = 0.f;
#pragma unroll
        for (int w = 0; w < 8; w++) { ts += red1[w]; tss += red2[w]; }
        float mean = ts * (1.0f / E_);
        float var  = tss * (1.0f / E_) - mean * mean;
        s_mean = mean;
        s_rstd = rsqrtf(var + 1e-5f);
    }
    __syncthreads();
    const float mean = s_mean, rstd = s_rstd;

    const float4 gv = ((const float4*)g)[tid];
    const float4 bv = ((const float4*)beta)[tid];
    float4 o;
    o.x = (v0 - mean) * rstd * gv.x + bv.x;
    o.y = (v1 - mean) * rstd * gv.y + bv.y;
    o.z = (v2 - mean) * rstd * gv.z + bv.z;
    o.w = (v3 - mean) * rstd * gv.w + bv.w;
    ((float4*)(out + (size_t)row * E_))[tid] = o;
    if (EMIT) {
        const size_t off = (size_t)row * E_ + tid * 4;
        *(__half2*)(oh + off)     = __floats2half2_rn(o.x, o.y);
        *(__half2*)(oh + off + 2) = __floats2half2_rn(o.z, o.w);
    }
}

// ============================================================================
// Launch
// ============================================================================
extern "C" void kernel_launch(void* const* d_in, const int* in_sizes, int n_in,
                              void* d_out, int out_size) {
    const float* x     = (const float*)d_in[0];
    const float* w_qkv = (const float*)d_in[1];
    const float* b_qkv = (const float*)d_in[2];
    const float* w_out = (const float*)d_in[3];
    const float* b_out = (const float*)d_in[4];
    const float* g1    = (const float*)d_in[5];
    const float* beta1 = (const float*)d_in[6];
    const float* g2    = (const float*)d_in[7];
    const float* beta2 = (const float*)d_in[8];
    const float* w1    = (const float*)d_in[9];
    const float* bf1   = (const float*)d_in[10];
    const float* w2    = (const float*)d_in[11];
    const float* bf2   = (const float*)d_in[12];
    float* out = (float*)d_out;

    float *tmp, *x1;
    cudaGetSymbolAddress((void**)&tmp,  g_tmp);
    cudaGetSymbolAddress((void**)&x1,   g_x1);

    __half *xh, *qkvh, *qkvl, *ctxh, *x1h, *hh;
    __half *wqkvh, *wouth, *w1h, *w2h;
    cudaGetSymbolAddress((void**)&xh, g_xh);
    cudaGetSymbolAddress((void**)&qkvh, g_qkvh);   cudaGetSymbolAddress((void**)&qkvl, g_qkvl);
    cudaGetSymbolAddress((void**)&ctxh, g_ctxh);
    cudaGetSymbolAddress((void**)&x1h, g_x1h);
    cudaGetSymbolAddress((void**)&hh, g_hh);
    cudaGetSymbolAddress((void**)&wqkvh, g_wqkvh);
    cudaGetSymbolAddress((void**)&wouth, g_wouth);
    cudaGetSymbolAddress((void**)&w1h, g_w1h);
    cudaGetSymbolAddress((void**)&w2h, g_w2h);

    cudaFuncSetAttribute(attn_tc, cudaFuncAttributeMaxDynamicSharedMemorySize, ASMEM_TOTAL);
    cudaFuncSetAttribute(mma_gemm<0,0,0>, cudaFuncAttributeMaxDynamicSharedMemorySize, GSMEM_TOTAL);
    cudaFuncSetAttribute(mma_gemm<0,1,1>, cudaFuncAttributeMaxDynamicSharedMemorySize, GSMEM_TOTAL);
    cudaFuncSetAttribute(mma_gemm<1,2,0>, cudaFuncAttributeMaxDynamicSharedMemorySize, GSMEM_TOTAL);

    dim3 thr(256);

    // 0: weights + x -> fp16  (16384 blocks: x needs 4096, not 1024!)
    conv_kernel<<<16384, thr>>>(w_qkv, w_out, w1, w2, x,
                                wqkvh, wouth, w1h, w2h, xh);

    // 1: qkv = x @ w_qkv^T + b_qkv -> fp16 hi/lo (Q pre-scaled)
    mma_gemm<0,1,1><<<dim3(3 * E_ / 128, M_ / 128), thr, GSMEM_TOTAL>>>(
        xh, wqkvh, b_qkv, nullptr, qkvh, qkvl, M_, 3 * E_, E_);

    // 2: flash attention -> ctx (fp16 hi)
    attn_tc<<<dim3(S_ / 128, H_, B_), thr, ASMEM_TOTAL>>>(qkvh, qkvl, ctxh);

    // 3: out-proj (fp32 out)
    mma_gemm<0,0,0><<<dim3(E_ / 128, M_ / 128), thr, GSMEM_TOTAL>>>(
        ctxh, wouth, b_out, tmp, nullptr, nullptr, M_, E_, E_);

    // 4: residual + LN -> x1 (+ fp16)
    add_ln_kernel<1><<<M_, thr>>>(x, tmp, g1, beta1, x1, x1h);

    // 5: h = gelu(x1 @ w1^T + bf1) -> fp16
    mma_gemm<1,2,0><<<dim3(FF_ / 128, M_ / 128), thr, GSMEM_TOTAL>>>(
        x1h, w1h, bf1, nullptr, hh, nullptr, M_, FF_, E_);

    // 6: ffn2 (fp32 out)
    mma_gemm<0,0,0><<<dim3(E_ / 128, M_ / 128), thr, GSMEM_TOTAL>>>(
        hh, w2h, bf2, tmp, nullptr, nullptr, M_, E_, FF_);

    // 7: residual + LN -> out
    add_ln_kernel<0><<<M_, thr>>>(x1, tmp, g2, beta2, out, nullptr);
}